// round 1
// baseline (speedup 1.0000x reference)
#include <cuda_runtime.h>
#include <cstdint>

typedef unsigned long long ull;

// Problem constants (fixed for this problem instance)
#define HH   128
#define HH2  256
#define G3   384
#define RMAX 8
#define NMAX 100000
#define EMAX 50000

// GRU tile config
#define ME   64     // edges per tile
#define CT   32     // output columns per block
#define KC   32     // k-chunk
#define TPB  256
#define WST  97     // padded row stride for weight smem (96+1)
#define XST  66     // padded row stride for transposed X smem (64+2, keeps 8B align)

// -------- scratch (device globals; no runtime allocation) --------
__device__ int   g_lastpos[RMAX * NMAX];
__device__ int   g_cnt[RMAX];
__device__ int   g_off[RMAX + 1];
__device__ int   g_cursor[RMAX];
__device__ int   g_order[EMAX];
__device__ float g_x[(size_t)EMAX * HH2];
__device__ float g_encT[RMAX * 64 * HH];   // [r][t][h], T<=64

// -------- helpers --------
__device__ __forceinline__ ull pack2(float w) {
    ull r; unsigned int b = __float_as_uint(w);
    asm("mov.b64 %0, {%1, %1};" : "=l"(r) : "r"(b));
    return r;
}
__device__ __forceinline__ void fma2(ull &d, ull a, ull b) {
    asm("fma.rn.f32x2 %0, %1, %2, %0;" : "+l"(d) : "l"(a), "l"(b));
}
__device__ __forceinline__ float2 unpack2(ull v) {
    float2 f; asm("mov.b64 {%0, %1}, %2;" : "=f"(f.x), "=f"(f.y) : "l"(v));
    return f;
}

// -------- kernels --------
__global__ void k_copy(const float4* __restrict__ in, float4* __restrict__ out, size_t n4) {
    size_t i = (size_t)blockIdx.x * blockDim.x + threadIdx.x;
    size_t stride = (size_t)gridDim.x * blockDim.x;
    for (; i < n4; i += stride) out[i] = in[i];
}

__global__ void k_init(int total) {
    int i = blockIdx.x * blockDim.x + threadIdx.x;
    int stride = gridDim.x * blockDim.x;
    for (; i < total; i += stride) g_lastpos[i] = -1;
    if (blockIdx.x == 0 && threadIdx.x < RMAX) {
        g_cnt[threadIdx.x] = 0;
        g_cursor[threadIdx.x] = 0;
    }
}

__global__ void k_encT(const float* __restrict__ encW, const float* __restrict__ encb,
                       int R, int T) {
    int i = blockIdx.x * blockDim.x + threadIdx.x;
    int total = R * T * HH;
    if (i >= total) return;
    int h = i % HH;
    int t = (i / HH) % T;
    int r = i / (HH * T);
    g_encT[i] = encW[(size_t)(r * HH + h) * T + t] + encb[r * HH + h];
}

__global__ void k_count(const int* __restrict__ rel, const int* __restrict__ src,
                        int E, int N) {
    __shared__ int sc[RMAX];
    if (threadIdx.x < RMAX) sc[threadIdx.x] = 0;
    __syncthreads();
    int i = blockIdx.x * blockDim.x + threadIdx.x;
    if (i < E) {
        int r = rel[i];
        atomicMax(&g_lastpos[(size_t)r * N + src[i]], i);
        atomicAdd(&sc[r], 1);
    }
    __syncthreads();
    if (threadIdx.x < RMAX && sc[threadIdx.x])
        atomicAdd(&g_cnt[threadIdx.x], sc[threadIdx.x]);
}

__global__ void k_scan(int R) {
    if (threadIdx.x == 0) {
        int acc = 0;
        for (int r = 0; r < R; r++) {
            g_off[r] = acc;
            g_cursor[r] = acc;
            acc += g_cnt[r];
        }
        g_off[R] = acc;
    }
}

__global__ void k_order(const int* __restrict__ rel, int E) {
    __shared__ int sc[RMAX], sbase[RMAX];
    if (threadIdx.x < RMAX) sc[threadIdx.x] = 0;
    __syncthreads();
    int i = blockIdx.x * blockDim.x + threadIdx.x;
    int r = 0, pos = 0;
    bool valid = (i < E);
    if (valid) {
        r = rel[i];
        pos = atomicAdd(&sc[r], 1);
    }
    __syncthreads();
    if (threadIdx.x < RMAX && sc[threadIdx.x])
        sbase[threadIdx.x] = atomicAdd(&g_cursor[threadIdx.x], sc[threadIdx.x]);
    __syncthreads();
    if (valid) g_order[sbase[r] + pos] = i;
}

__global__ void k_build_x(const float* __restrict__ prev, const int* __restrict__ src,
                          const int* __restrict__ dst, const int* __restrict__ rel,
                          const int* __restrict__ t_edge, const int* __restrict__ ctp,
                          int E, int N, int T) {
    int i = blockIdx.x * blockDim.x + threadIdx.x;
    if (i >= E * HH) return;
    int e = i >> 7;
    int h = i & (HH - 1);
    int r = rel[e];
    int ct = ctp ? ctp[0] : 100;
    int b = min(ct - t_edge[e], T - 1);
    float enc = g_encT[(r * T + b) * HH + h];
    float uj = prev[((size_t)r * N + dst[e]) * HH + h];
    float ui = prev[((size_t)r * N + src[e]) * HH + h];
    g_x[(size_t)e * HH2 + h]      = enc + uj;
    g_x[(size_t)e * HH2 + HH + h] = ui;
}

// Dynamic smem layout:
//  float sXT[256 * XST]     (transposed X tile: [k][m], padded)
//  float sWih[KC * WST]
//  float sWhh[KC * WST]
//  int   sEid[ME], sSrc[ME]
#define SXT_F   (HH2 * XST)
#define SW_F    (KC * WST)
#define SMEM_BYTES ((SXT_F + 2 * SW_F) * 4 + 2 * ME * 4)

__global__ void __launch_bounds__(TPB)
k_gru(const float* __restrict__ W_ih, const float* __restrict__ W_hh,
      const float* __restrict__ b_ih, const float* __restrict__ b_hh,
      const int* __restrict__ src, float* __restrict__ out, int N) {
    int r = blockIdx.x;
    int begin = g_off[r], end = g_off[r + 1];
    int base = begin + blockIdx.y * ME;
    if (base >= end) return;
    int mE = min(ME, end - base);
    int c0 = blockIdx.z * CT;
    int tid = threadIdx.x;
    int c = tid & 31;
    int m8 = tid >> 5;
    int mbase = m8 * 8;

    extern __shared__ float sm[];
    float* sXT  = sm;
    float* sWih = sXT + SXT_F;
    float* sWhh = sWih + SW_F;
    int*   sEid = (int*)(sWhh + SW_F);
    int*   sSrc = sEid + ME;

    // edge ids + srcs
    for (int m = tid; m < ME; m += TPB) {
        int e = (m < mE) ? g_order[base + m] : -1;
        sEid[m] = e;
        sSrc[m] = (e >= 0) ? src[e] : 0;
    }
    __syncthreads();

    // load X tile transposed: sXT[k][m]
    for (int i = tid; i < ME * HH2; i += TPB) {
        int m = i >> 8;        // i = m*256 + k
        int k = i & 255;
        float v = 0.f;
        if (m < mE) v = g_x[(size_t)sEid[m] * HH2 + k];
        sXT[k * XST + m] = v;
    }

    ull a_ir[4] = {0,0,0,0}, a_iz[4] = {0,0,0,0}, a_in[4] = {0,0,0,0};
    ull a_hr[4] = {0,0,0,0}, a_hz[4] = {0,0,0,0}, a_hn[4] = {0,0,0,0};

    const float* Wih_r = W_ih + (size_t)r * G3 * HH2;
    const float* Whh_r = W_hh + (size_t)r * G3 * HH;

    // phase 1: k in [0,128) — input gates only
    for (int kc = 0; kc < HH; kc += KC) {
        __syncthreads();
        #pragma unroll
        for (int i2 = 0; i2 < 12; i2++) {
            int idx = tid + i2 * TPB;       // 0..3071
            int c96 = idx >> 5;
            int kk  = idx & 31;
            int row = (c96 >> 5) * HH + c0 + (c96 & 31);
            sWih[kk * WST + c96] = Wih_r[(size_t)row * HH2 + kc + kk];
        }
        __syncthreads();
        #pragma unroll 4
        for (int kk = 0; kk < KC; kk++) {
            const float* wrow = &sWih[kk * WST];
            ull wr2 = pack2(wrow[c]);
            ull wz2 = pack2(wrow[32 + c]);
            ull wn2 = pack2(wrow[64 + c]);
            const ull* xrow = (const ull*)&sXT[(kc + kk) * XST + mbase];
            #pragma unroll
            for (int j2 = 0; j2 < 4; j2++) {
                ull x2 = xrow[j2];
                fma2(a_ir[j2], x2, wr2);
                fma2(a_iz[j2], x2, wz2);
                fma2(a_in[j2], x2, wn2);
            }
        }
    }

    // phase 2: k in [128,256) — input gates + hidden gates (W_hh on u_i = x[128:256])
    for (int kc = HH; kc < HH2; kc += KC) {
        __syncthreads();
        #pragma unroll
        for (int i2 = 0; i2 < 12; i2++) {
            int idx = tid + i2 * TPB;
            int c96 = idx >> 5;
            int kk  = idx & 31;
            int row = (c96 >> 5) * HH + c0 + (c96 & 31);
            sWih[kk * WST + c96] = Wih_r[(size_t)row * HH2 + kc + kk];
            sWhh[kk * WST + c96] = Whh_r[(size_t)row * HH + (kc - HH) + kk];
        }
        __syncthreads();
        #pragma unroll 2
        for (int kk = 0; kk < KC; kk++) {
            const float* wrow  = &sWih[kk * WST];
            const float* whrow = &sWhh[kk * WST];
            ull wr2  = pack2(wrow[c]);
            ull wz2  = pack2(wrow[32 + c]);
            ull wn2  = pack2(wrow[64 + c]);
            ull whr2 = pack2(whrow[c]);
            ull whz2 = pack2(whrow[32 + c]);
            ull whn2 = pack2(whrow[64 + c]);
            const ull* xrow = (const ull*)&sXT[(kc + kk) * XST + mbase];
            #pragma unroll
            for (int j2 = 0; j2 < 4; j2++) {
                ull x2 = xrow[j2];
                fma2(a_ir[j2], x2, wr2);
                fma2(a_iz[j2], x2, wz2);
                fma2(a_in[j2], x2, wn2);
                fma2(a_hr[j2], x2, whr2);
                fma2(a_hz[j2], x2, whz2);
                fma2(a_hn[j2], x2, whn2);
            }
        }
    }

    // epilogue: GRU nonlinearity + last-edge-wins scatter
    int col = c0 + c;
    const float* bi = b_ih + r * G3;
    const float* bh = b_hh + r * G3;
    float bir = bi[col], biz = bi[HH + col], bin_ = bi[2 * HH + col];
    float bhr = bh[col], bhz = bh[HH + col], bhn  = bh[2 * HH + col];
    size_t lpb = (size_t)r * N;

    #pragma unroll
    for (int j2 = 0; j2 < 4; j2++) {
        float2 ir2 = unpack2(a_ir[j2]);
        float2 iz2 = unpack2(a_iz[j2]);
        float2 in2 = unpack2(a_in[j2]);
        float2 hr2 = unpack2(a_hr[j2]);
        float2 hz2 = unpack2(a_hz[j2]);
        float2 hn2 = unpack2(a_hn[j2]);
        #pragma unroll
        for (int hf = 0; hf < 2; hf++) {
            int m = mbase + j2 * 2 + hf;
            if (m >= mE) continue;
            float ir = hf ? ir2.y : ir2.x;
            float iz = hf ? iz2.y : iz2.x;
            float in_ = hf ? in2.y : in2.x;
            float hr = hf ? hr2.y : hr2.x;
            float hz = hf ? hz2.y : hz2.x;
            float hn = hf ? hn2.y : hn2.x;
            float rg = 1.f / (1.f + expf(-(ir + bir + hr + bhr)));
            float zg = 1.f / (1.f + expf(-(iz + biz + hz + bhz)));
            float ng = tanhf(in_ + bin_ + rg * (hn + bhn));
            float hp = sXT[(HH + col) * XST + m];
            float hv = (1.f - zg) * ng + zg * hp;
            int e = sEid[m];
            int s = sSrc[m];
            if (g_lastpos[lpb + s] == e)
                out[(lpb + s) * HH + col] = hv;
        }
    }
}

// -------- launch --------
extern "C" void kernel_launch(void* const* d_in, const int* in_sizes, int n_in,
                              void* d_out, int out_size) {
    const float* prev  = (const float*)d_in[0];
    const float* encW  = (const float*)d_in[1];
    const float* encb  = (const float*)d_in[2];
    const float* W_ih  = (const float*)d_in[3];
    const float* W_hh  = (const float*)d_in[4];
    const float* b_ih  = (const float*)d_in[5];
    const float* b_hh  = (const float*)d_in[6];
    const int*   src   = (const int*)d_in[7];
    const int*   dst   = (const int*)d_in[8];
    const int*   rel   = (const int*)d_in[9];
    const int*   t_edg = (const int*)d_in[10];
    const int*   ctp   = (n_in > 11) ? (const int*)d_in[11] : nullptr;
    float* out = (float*)d_out;

    int E  = in_sizes[7];
    int b_ih_n = in_sizes[5];                 // R*3H
    int W_hh_n = in_sizes[4];                 // R*3H*H
    int Hd = W_hh_n / b_ih_n;                 // 128
    int Rd = b_ih_n / (3 * Hd);               // 8
    long long prevN = in_sizes[0];
    int Nd = (int)(prevN / ((long long)Rd * Hd));
    int Td = in_sizes[1] / (2 * Rd * Hd);

    // 1) copy prev -> out
    size_t n4 = (size_t)out_size / 4;
    k_copy<<<4736, 256>>>((const float4*)prev, (float4*)out, n4);

    // 2) reset scratch
    int totalLP = Rd * Nd;
    k_init<<<(totalLP + 255) / 256, 256>>>(totalLP);

    // 3) transposed encoder table
    int encN = Rd * Td * Hd;
    k_encT<<<(encN + 255) / 256, 256>>>(encW, encb, Rd, Td);

    // 4) counts + lastpos
    k_count<<<(E + 255) / 256, 256>>>(rel, src, E, Nd);

    // 5) scan
    k_scan<<<1, 32>>>(Rd);

    // 6) group edges by relation
    k_order<<<(E + 255) / 256, 256>>>(rel, E);

    // 7) build x = [enc + u_j, u_i]
    int bxN = E * Hd;
    k_build_x<<<(bxN + 255) / 256, 256>>>(prev, src, dst, rel, t_edg, ctp, E, Nd, Td);

    // 8) fused GRU GEMM + scatter
    cudaFuncSetAttribute(k_gru, cudaFuncAttributeMaxDynamicSharedMemorySize, SMEM_BYTES);
    dim3 grid(Rd, (E + ME - 1) / ME, Hd / CT);
    k_gru<<<grid, TPB, SMEM_BYTES>>>(W_ih, W_hh, b_ih, b_hh, src, out, Nd);
}

// round 2
// speedup vs baseline: 1.3389x; 1.3389x over previous
#include <cuda_runtime.h>
#include <cstdint>

typedef unsigned long long ull;

// Problem constants
#define HH   128
#define HH2  256
#define G3   384
#define RMAX 8
#define NMAX 100000
#define EMAX 50000

// GRU tile config
#define ME   64     // edges per tile
#define KC   32     // k-chunk
#define TPB  256
#define XST  65     // padded row stride for transposed X smem (conflict-free STS)
#define WCS  194    // sWc row stride (192 + 2, keeps 8B align)
#define HNS  66     // sHn row stride (64 + 2)

// -------- scratch (device globals; no runtime allocation) --------
__device__ int   g_lastpos[RMAX * NMAX];
__device__ int   g_cnt[RMAX];
__device__ int   g_off[RMAX + 1];
__device__ int   g_cursor[RMAX];
__device__ int   g_order[EMAX];
__device__ float g_x[(size_t)EMAX * HH2];
__device__ float g_encT[RMAX * 64 * HH];              // [r][t][h], T<=64
__device__ float g_WcT[(size_t)RMAX * HH2 * G3];      // [r][k][g*128+col], W_hh r/z folded
__device__ float g_WhnT[(size_t)RMAX * HH * HH];      // [r][k][col]
__device__ float g_bc[RMAX * G3];                     // b_ih (+ b_hh for r,z)
__device__ float g_bhn[RMAX * HH];                    // b_hh n-gate

// -------- helpers --------
__device__ __forceinline__ ull pack2(float w) {
    ull r; unsigned int b = __float_as_uint(w);
    asm("mov.b64 %0, {%1, %1};" : "=l"(r) : "r"(b));
    return r;
}
__device__ __forceinline__ void fma2(ull &d, ull a, ull b) {
    asm("fma.rn.f32x2 %0, %1, %2, %0;" : "+l"(d) : "l"(a), "l"(b));
}
__device__ __forceinline__ float2 unpack2(ull v) {
    float2 f; asm("mov.b64 {%0, %1}, %2;" : "=f"(f.x), "=f"(f.y) : "l"(v));
    return f;
}

// -------- kernels --------
__global__ void k_copy(const float4* __restrict__ in, float4* __restrict__ out, size_t n4) {
    size_t i = (size_t)blockIdx.x * blockDim.x + threadIdx.x;
    size_t stride = (size_t)gridDim.x * blockDim.x;
    for (; i < n4; i += stride) out[i] = in[i];
}

__global__ void k_init(int total) {
    int i = blockIdx.x * blockDim.x + threadIdx.x;
    int stride = gridDim.x * blockDim.x;
    for (; i < total; i += stride) g_lastpos[i] = -1;
    if (blockIdx.x == 0 && threadIdx.x < RMAX) {
        g_cnt[threadIdx.x] = 0;
        g_cursor[threadIdx.x] = 0;
    }
}

__global__ void k_encT(const float* __restrict__ encW, const float* __restrict__ encb,
                       int R, int T) {
    int i = blockIdx.x * blockDim.x + threadIdx.x;
    int total = R * T * HH;
    if (i >= total) return;
    int h = i % HH;
    int t = (i / HH) % T;
    int r = i / (HH * T);
    g_encT[i] = encW[(size_t)(r * HH + h) * T + t] + encb[r * HH + h];
}

// Fold W_hh r/z into W_ih second half; transpose to k-major for coalesced tile loads.
__global__ void k_prep(const float* __restrict__ W_ih, const float* __restrict__ W_hh,
                       const float* __restrict__ b_ih, const float* __restrict__ b_hh,
                       int R) {
    int i = blockIdx.x * blockDim.x + threadIdx.x;
    int totalWc = R * HH2 * G3;
    if (i < totalWc) {
        int col3 = i % G3;            // g*128+col (row of W_ih)
        int k    = (i / G3) % HH2;
        int r    = i / (G3 * HH2);
        int g    = col3 >> 7;
        float v = W_ih[((size_t)r * G3 + col3) * HH2 + k];
        if (g < 2 && k >= HH) v += W_hh[((size_t)r * G3 + col3) * HH + (k - HH)];
        g_WcT[i] = v;
    }
    int j = i - totalWc;
    int totalHn = R * HH * HH;
    if (j >= 0 && j < totalHn) {
        int col = j % HH;
        int k   = (j / HH) % HH;
        int r   = j / (HH * HH);
        g_WhnT[j] = W_hh[((size_t)r * G3 + 2 * HH + col) * HH + k];
    }
    if (i < R * G3) {
        int col3 = i % G3;
        int r    = i / G3;
        int g    = col3 >> 7;
        g_bc[i] = b_ih[i] + ((g < 2) ? b_hh[i] : 0.f);
        if (g == 2) g_bhn[r * HH + (col3 & 127)] = b_hh[i];
    }
}

__global__ void k_count(const int* __restrict__ rel, const int* __restrict__ src,
                        int E, int N) {
    __shared__ int sc[RMAX];
    if (threadIdx.x < RMAX) sc[threadIdx.x] = 0;
    __syncthreads();
    int i = blockIdx.x * blockDim.x + threadIdx.x;
    if (i < E) {
        int r = rel[i];
        atomicMax(&g_lastpos[(size_t)r * N + src[i]], i);
        atomicAdd(&sc[r], 1);
    }
    __syncthreads();
    if (threadIdx.x < RMAX && sc[threadIdx.x])
        atomicAdd(&g_cnt[threadIdx.x], sc[threadIdx.x]);
}

__global__ void k_scan(int R) {
    if (threadIdx.x == 0) {
        int acc = 0;
        for (int r = 0; r < R; r++) {
            g_off[r] = acc;
            g_cursor[r] = acc;
            acc += g_cnt[r];
        }
        g_off[R] = acc;
    }
}

__global__ void k_order(const int* __restrict__ rel, int E) {
    __shared__ int sc[RMAX], sbase[RMAX];
    if (threadIdx.x < RMAX) sc[threadIdx.x] = 0;
    __syncthreads();
    int i = blockIdx.x * blockDim.x + threadIdx.x;
    int r = 0, pos = 0;
    bool valid = (i < E);
    if (valid) {
        r = rel[i];
        pos = atomicAdd(&sc[r], 1);
    }
    __syncthreads();
    if (threadIdx.x < RMAX && sc[threadIdx.x])
        sbase[threadIdx.x] = atomicAdd(&g_cursor[threadIdx.x], sc[threadIdx.x]);
    __syncthreads();
    if (valid) g_order[sbase[r] + pos] = i;
}

__global__ void k_build_x(const float* __restrict__ prev, const int* __restrict__ src,
                          const int* __restrict__ dst, const int* __restrict__ rel,
                          const int* __restrict__ t_edge, const int* __restrict__ ctp,
                          int E, int N, int T) {
    int i = blockIdx.x * blockDim.x + threadIdx.x;
    if (i >= E * HH) return;
    int e = i >> 7;
    int h = i & (HH - 1);
    int r = rel[e];
    int ct = ctp ? ctp[0] : 100;
    int b = min(ct - t_edge[e], T - 1);
    float enc = g_encT[(r * T + b) * HH + h];
    float uj = prev[((size_t)r * N + dst[e]) * HH + h];
    float ui = prev[((size_t)r * N + src[e]) * HH + h];
    g_x[(size_t)e * HH2 + h]      = enc + uj;
    g_x[(size_t)e * HH2 + HH + h] = ui;
}

// Dynamic smem layout
#define SXT_F  (HH2 * XST)   // 256*65
#define SWC_F  (KC * WCS)    // 32*194
#define SHN_F  (KC * HNS)    // 32*66
#define SMEM_BYTES ((SXT_F + SWC_F + SHN_F) * 4 + 2 * ME * 4)

__global__ void __launch_bounds__(TPB, 2)
k_gru(const int* __restrict__ src, float* __restrict__ out, int N) {
    int r = blockIdx.x;
    int begin = g_off[r], end = g_off[r + 1];
    int base = begin + blockIdx.y * ME;
    if (base >= end) return;
    int mE = min(ME, end - base);
    int c0 = blockIdx.z * 64;           // 64 output columns per block (2 per lane)
    int tid = threadIdx.x;
    int c = tid & 31;                   // lane -> column pair (c0+2c, c0+2c+1)
    int mbase = (tid >> 5) * 8;         // warp -> 8 edges

    extern __shared__ float sm[];
    float* sXT = sm;                    // [k][m], stride XST
    float* sWc = sXT + SXT_F;           // [kk][192], stride WCS
    float* sHn = sWc + SWC_F;           // [kk][64],  stride HNS
    int*   sEid = (int*)(sHn + SHN_F);
    int*   sSrc = sEid + ME;

    for (int m = tid; m < ME; m += TPB) {
        int e = (m < mE) ? g_order[base + m] : -1;
        sEid[m] = e;
        sSrc[m] = (e >= 0) ? src[e] : 0;
    }
    __syncthreads();
    for (int i = tid; i < ME * HH2; i += TPB) {
        int m = i >> 8;
        int k = i & 255;
        sXT[k * XST + m] = (m < mE) ? g_x[(size_t)sEid[m] * HH2 + k] : 0.f;
    }

    ull ar[8] = {0,0,0,0,0,0,0,0}, az[8] = {0,0,0,0,0,0,0,0};
    ull an[8] = {0,0,0,0,0,0,0,0}, ah[8] = {0,0,0,0,0,0,0,0};

    const float* WcT = g_WcT + (size_t)r * HH2 * G3;
    const float* HnT = g_WhnT + (size_t)r * HH * HH;

    // phase 1: k in [0,128) — combined gates only
    for (int kc = 0; kc < HH; kc += KC) {
        __syncthreads();
        #pragma unroll
        for (int t = 0; t < 24; t++) {
            int idx = tid + t * TPB;          // 0..6143
            int kk = idx / 192;
            int cc = idx - kk * 192;
            int g  = cc >> 6;
            int cl = cc & 63;
            sWc[kk * WCS + cc] = WcT[(size_t)(kc + kk) * G3 + g * HH + c0 + cl];
        }
        __syncthreads();
        #pragma unroll 2
        for (int kk = 0; kk < KC; kk++) {
            const float* xr = &sXT[(kc + kk) * XST];
            ull wr = *(const ull*)&sWc[kk * WCS + 2 * c];
            ull wz = *(const ull*)&sWc[kk * WCS + 64 + 2 * c];
            ull wn = *(const ull*)&sWc[kk * WCS + 128 + 2 * c];
            #pragma unroll
            for (int j = 0; j < 8; j++) {
                ull x2 = pack2(xr[mbase + j]);
                fma2(ar[j], wr, x2);
                fma2(az[j], wz, x2);
                fma2(an[j], wn, x2);
            }
        }
    }

    // phase 2: k in [128,256) — combined gates + h_n
    for (int kc = HH; kc < HH2; kc += KC) {
        __syncthreads();
        #pragma unroll
        for (int t = 0; t < 24; t++) {
            int idx = tid + t * TPB;
            int kk = idx / 192;
            int cc = idx - kk * 192;
            int g  = cc >> 6;
            int cl = cc & 63;
            sWc[kk * WCS + cc] = WcT[(size_t)(kc + kk) * G3 + g * HH + c0 + cl];
        }
        #pragma unroll
        for (int t = 0; t < 8; t++) {
            int idx = tid + t * TPB;          // 0..2047
            int kk = idx >> 6;
            int cl = idx & 63;
            sHn[kk * HNS + cl] = HnT[(size_t)(kc - HH + kk) * HH + c0 + cl];
        }
        __syncthreads();
        #pragma unroll 2
        for (int kk = 0; kk < KC; kk++) {
            const float* xr = &sXT[(kc + kk) * XST];
            ull wr = *(const ull*)&sWc[kk * WCS + 2 * c];
            ull wz = *(const ull*)&sWc[kk * WCS + 64 + 2 * c];
            ull wn = *(const ull*)&sWc[kk * WCS + 128 + 2 * c];
            ull wh = *(const ull*)&sHn[kk * HNS + 2 * c];
            #pragma unroll
            for (int j = 0; j < 8; j++) {
                ull x2 = pack2(xr[mbase + j]);
                fma2(ar[j], wr, x2);
                fma2(az[j], wz, x2);
                fma2(an[j], wn, x2);
                fma2(ah[j], wh, x2);
            }
        }
    }

    // epilogue: nonlinearity + last-edge-wins scatter (2 cols per thread)
    int col0 = c0 + 2 * c;
    float2 bcr = *(const float2*)&g_bc[r * G3 + col0];
    float2 bcz = *(const float2*)&g_bc[r * G3 + HH + col0];
    float2 bcn = *(const float2*)&g_bc[r * G3 + 2 * HH + col0];
    float2 bh2 = *(const float2*)&g_bhn[r * HH + col0];
    size_t lpb = (size_t)r * N;

    #pragma unroll
    for (int j = 0; j < 8; j++) {
        int m = mbase + j;
        if (m >= mE) break;
        float2 vr = unpack2(ar[j]);
        float2 vz = unpack2(az[j]);
        float2 vn = unpack2(an[j]);
        float2 vh = unpack2(ah[j]);
        float rg0 = 1.f / (1.f + expf(-(vr.x + bcr.x)));
        float rg1 = 1.f / (1.f + expf(-(vr.y + bcr.y)));
        float zg0 = 1.f / (1.f + expf(-(vz.x + bcz.x)));
        float zg1 = 1.f / (1.f + expf(-(vz.y + bcz.y)));
        float ng0 = tanhf(vn.x + bcn.x + rg0 * (vh.x + bh2.x));
        float ng1 = tanhf(vn.y + bcn.y + rg1 * (vh.y + bh2.y));
        float hp0 = sXT[(HH + col0) * XST + m];
        float hp1 = sXT[(HH + col0 + 1) * XST + m];
        float2 hv;
        hv.x = (1.f - zg0) * ng0 + zg0 * hp0;
        hv.y = (1.f - zg1) * ng1 + zg1 * hp1;
        int e = sEid[m];
        int s = sSrc[m];
        if (g_lastpos[lpb + s] == e)
            *(float2*)&out[(lpb + s) * HH + col0] = hv;
    }
}

// -------- launch --------
extern "C" void kernel_launch(void* const* d_in, const int* in_sizes, int n_in,
                              void* d_out, int out_size) {
    const float* prev  = (const float*)d_in[0];
    const float* encW  = (const float*)d_in[1];
    const float* encb  = (const float*)d_in[2];
    const float* W_ih  = (const float*)d_in[3];
    const float* W_hh  = (const float*)d_in[4];
    const float* b_ih  = (const float*)d_in[5];
    const float* b_hh  = (const float*)d_in[6];
    const int*   src   = (const int*)d_in[7];
    const int*   dst   = (const int*)d_in[8];
    const int*   rel   = (const int*)d_in[9];
    const int*   t_edg = (const int*)d_in[10];
    const int*   ctp   = (n_in > 11) ? (const int*)d_in[11] : nullptr;
    float* out = (float*)d_out;

    int E  = in_sizes[7];
    int b_ih_n = in_sizes[5];                 // R*3H
    int W_hh_n = in_sizes[4];                 // R*3H*H
    int Hd = W_hh_n / b_ih_n;                 // 128
    int Rd = b_ih_n / (3 * Hd);               // 8
    long long prevN = in_sizes[0];
    int Nd = (int)(prevN / ((long long)Rd * Hd));
    int Td = in_sizes[1] / (2 * Rd * Hd);

    // 1) copy prev -> out
    size_t n4 = (size_t)out_size / 4;
    k_copy<<<4736, 256>>>((const float4*)prev, (float4*)out, n4);

    // 2) reset scratch
    int totalLP = Rd * Nd;
    k_init<<<(totalLP + 255) / 256, 256>>>(totalLP);

    // 3) transposed encoder table
    int encN = Rd * Td * Hd;
    k_encT<<<(encN + 255) / 256, 256>>>(encW, encb, Rd, Td);

    // 4) fold + transpose weights
    int prepN = Rd * 2 * Hd * 3 * Hd + Rd * Hd * Hd;
    k_prep<<<(prepN + 255) / 256, 256>>>(W_ih, W_hh, b_ih, b_hh, Rd);

    // 5) counts + lastpos
    k_count<<<(E + 255) / 256, 256>>>(rel, src, E, Nd);

    // 6) scan
    k_scan<<<1, 32>>>(Rd);

    // 7) group edges by relation
    k_order<<<(E + 255) / 256, 256>>>(rel, E);

    // 8) build x = [enc + u_j, u_i]
    int bxN = E * Hd;
    k_build_x<<<(bxN + 255) / 256, 256>>>(prev, src, dst, rel, t_edg, ctp, E, Nd, Td);

    // 9) fused GRU GEMM + scatter
    cudaFuncSetAttribute(k_gru, cudaFuncAttributeMaxDynamicSharedMemorySize, SMEM_BYTES);
    dim3 grid(Rd, (E + ME - 1) / ME, Hd / 64);
    k_gru<<<grid, TPB, SMEM_BYTES>>>(src, out, Nd);
}

// round 4
// speedup vs baseline: 1.3553x; 1.0122x over previous
#include <cuda_runtime.h>
#include <cstdint>

typedef unsigned long long ull;

// Problem constants
#define HH   128
#define HH2  256
#define G3   384
#define NB   512          // gate rows: 256 folded r/z + 128 n + 128 hn
#define RMAX 8
#define NMAX 100000
#define EMAX 50000

// mma tile config
#define MT_E   128        // edges per CTA tile
#define TPB    256
#define XS     260        // smem X row stride (floats): 260 mod 32 = 4 -> frag LDS conflict-free
// A-frag global layout: [r][nhalf][ks=32][mt=16][hl=2][lane=32] float4
#define AFRAG_PER_NH 32768   // 32*16*2*32 float4s

// -------- scratch (device globals; no runtime allocation) --------
__device__ int   g_lastpos[RMAX * NMAX];
__device__ int   g_cnt[RMAX];
__device__ int   g_off[RMAX + 1];
__device__ int   g_cursor[RMAX];
__device__ int   g_order[EMAX];
__device__ float g_x[(size_t)EMAX * HH2];
__device__ float g_y[(size_t)EMAX * NB];
__device__ float g_encT[RMAX * 64 * HH];                     // [r][t][h], T<=64
__device__ float4 g_Afrag[(size_t)RMAX * 2 * AFRAG_PER_NH];  // frag-major weights (tf32 hi/lo)
__device__ float g_bc[RMAX * G3];                            // b_ih (+ b_hh for r,z)
__device__ float g_bhn[RMAX * HH];                           // b_hh n-gate

// -------- helpers --------
__device__ __forceinline__ float tf32hi(float v) {
    uint32_t b;
    asm("cvt.rna.tf32.f32 %0, %1;" : "=r"(b) : "f"(v));
    return __uint_as_float(b);
}
__device__ __forceinline__ void mma8(float* c, const uint32_t* a, uint32_t b0, uint32_t b1) {
    asm volatile(
        "mma.sync.aligned.m16n8k8.row.col.f32.tf32.tf32.f32 "
        "{%0,%1,%2,%3}, {%4,%5,%6,%7}, {%8,%9}, {%0,%1,%2,%3};"
        : "+f"(c[0]), "+f"(c[1]), "+f"(c[2]), "+f"(c[3])
        : "r"(a[0]), "r"(a[1]), "r"(a[2]), "r"(a[3]), "r"(b0), "r"(b1));
}

// -------- small kernels --------
__global__ void k_copy(const float4* __restrict__ in, float4* __restrict__ out, size_t n4) {
    size_t i = (size_t)blockIdx.x * blockDim.x + threadIdx.x;
    size_t stride = (size_t)gridDim.x * blockDim.x;
    for (; i < n4; i += stride) out[i] = in[i];
}

__global__ void k_init(int total) {
    int i = blockIdx.x * blockDim.x + threadIdx.x;
    int stride = gridDim.x * blockDim.x;
    for (; i < total; i += stride) g_lastpos[i] = -1;
    if (blockIdx.x == 0 && threadIdx.x < RMAX) {
        g_cnt[threadIdx.x] = 0;
        g_cursor[threadIdx.x] = 0;
    }
}

__global__ void k_encT(const float* __restrict__ encW, const float* __restrict__ encb,
                       int R, int T) {
    int i = blockIdx.x * blockDim.x + threadIdx.x;
    int total = R * T * HH;
    if (i >= total) return;
    int h = i % HH;
    int t = (i / HH) % T;
    int r = i / (HH * T);
    g_encT[i] = encW[(size_t)(r * HH + h) * T + t] + encb[r * HH + h];
}

// Build fragment-major tf32 hi/lo weight tensor + combined biases.
// Gate rows: 0-255 folded r/z (W_ih + W_hh for k>=128), 256-383 n (W_ih),
//            384-511 hn (W_hh n rows, zero for k<128).
__global__ void k_prep(const float* __restrict__ W_ih, const float* __restrict__ W_hh,
                       const float* __restrict__ b_ih, const float* __restrict__ b_hh,
                       int R) {
    int i = blockIdx.x * blockDim.x + threadIdx.x;
    int total = R * 2 * AFRAG_PER_NH;
    if (i < total) {
        int lane = i & 31;
        int hl   = (i >> 5) & 1;
        int mt   = (i >> 6) & 15;
        int ks   = (i >> 10) & 31;
        int nh   = (i >> 15) & 1;
        int r    = i >> 16;
        int g    = lane >> 2;
        int tig  = lane & 3;
        float4 v4;
        float* vp = (float*)&v4;
        #pragma unroll
        for (int j = 0; j < 4; j++) {
            int m_local = mt * 16 + (j & 1) * 8 + g;   // 0..255
            int k       = ks * 8 + (j >> 1) * 4 + tig; // 0..255
            int row = nh * 256 + m_local;              // 0..511
            float v;
            if (row < 2 * HH) {
                v = W_ih[((size_t)r * G3 + row) * HH2 + k];
                if (k >= HH) v += W_hh[((size_t)r * G3 + row) * HH + (k - HH)];
            } else if (row < G3) {
                v = W_ih[((size_t)r * G3 + row) * HH2 + k];
            } else {
                int col = row - G3;
                v = (k >= HH) ? W_hh[((size_t)r * G3 + 2 * HH + col) * HH + (k - HH)] : 0.f;
            }
            float hi = tf32hi(v);
            vp[j] = hl ? tf32hi(v - hi) : hi;
        }
        g_Afrag[i] = v4;
    }
    if (i < R * G3) {
        int col3 = i % G3;
        int r    = i / G3;
        int g    = col3 >> 7;
        g_bc[i] = b_ih[i] + ((g < 2) ? b_hh[i] : 0.f);
        if (g == 2) g_bhn[r * HH + (col3 & 127)] = b_hh[i];
    }
}

__global__ void k_count(const int* __restrict__ rel, const int* __restrict__ src,
                        int E, int N) {
    __shared__ int sc[RMAX];
    if (threadIdx.x < RMAX) sc[threadIdx.x] = 0;
    __syncthreads();
    int i = blockIdx.x * blockDim.x + threadIdx.x;
    if (i < E) {
        int r = rel[i];
        atomicMax(&g_lastpos[(size_t)r * N + src[i]], i);
        atomicAdd(&sc[r], 1);
    }
    __syncthreads();
    if (threadIdx.x < RMAX && sc[threadIdx.x])
        atomicAdd(&g_cnt[threadIdx.x], sc[threadIdx.x]);
}

__global__ void k_scan(int R) {
    if (threadIdx.x == 0) {
        int acc = 0;
        for (int r = 0; r < R; r++) {
            g_off[r] = acc;
            g_cursor[r] = acc;
            acc += g_cnt[r];
        }
        g_off[R] = acc;
    }
}

__global__ void k_order(const int* __restrict__ rel, int E) {
    __shared__ int sc[RMAX], sbase[RMAX];
    if (threadIdx.x < RMAX) sc[threadIdx.x] = 0;
    __syncthreads();
    int i = blockIdx.x * blockDim.x + threadIdx.x;
    int r = 0, pos = 0;
    bool valid = (i < E);
    if (valid) {
        r = rel[i];
        pos = atomicAdd(&sc[r], 1);
    }
    __syncthreads();
    if (threadIdx.x < RMAX && sc[threadIdx.x])
        sbase[threadIdx.x] = atomicAdd(&g_cursor[threadIdx.x], sc[threadIdx.x]);
    __syncthreads();
    if (valid) g_order[sbase[r] + pos] = i;
}

__global__ void k_build_x(const float* __restrict__ prev, const int* __restrict__ src,
                          const int* __restrict__ dst, const int* __restrict__ rel,
                          const int* __restrict__ t_edge, const int* __restrict__ ctp,
                          int E, int N, int T) {
    int i = blockIdx.x * blockDim.x + threadIdx.x;
    if (i >= E * HH) return;
    int e = i >> 7;
    int h = i & (HH - 1);
    int r = rel[e];
    int ct = ctp ? ctp[0] : 100;
    int b = min(ct - t_edge[e], T - 1);
    float enc = g_encT[(r * T + b) * HH + h];
    float uj = prev[((size_t)r * N + dst[e]) * HH + h];
    float ui = prev[((size_t)r * N + src[e]) * HH + h];
    g_x[(size_t)e * HH2 + h]      = enc + uj;
    g_x[(size_t)e * HH2 + HH + h] = ui;
}

// -------- tensor-core GEMM: Y[e, nh*256 .. +256] = X[e,:] . W^T (3xTF32) --------
// smem: sX [128 edges][XS floats] + sEid[128]
#define SMEM_MMA (MT_E * XS * 4 + MT_E * 4)

__global__ void __launch_bounds__(TPB, 1)
k_gru_mma() {
    int r  = blockIdx.x;
    int nh = blockIdx.z;
    int begin = g_off[r], end = g_off[r + 1];
    int base = begin + blockIdx.y * MT_E;
    if (base >= end) return;
    int mE = min(MT_E, end - base);
    int tid = threadIdx.x;
    int w = tid >> 5, lane = tid & 31;
    int g = lane >> 2, tig = lane & 3;

    extern __shared__ float sm[];
    float* sX  = sm;                       // [m][k] stride XS
    int* sEid  = (int*)(sm + MT_E * XS);

    if (tid < MT_E)
        sEid[tid] = (tid < mE) ? g_order[base + tid] : -1;
    __syncthreads();

    // gather X tile (row-major, coalesced)
    const float4* gx4 = (const float4*)g_x;
    #pragma unroll
    for (int it = 0; it < 32; it++) {
        int s = tid + it * TPB;            // 0..8191 float4 slots
        int row = s >> 6, j = s & 63;
        int e = sEid[row];
        float4 v = make_float4(0.f, 0.f, 0.f, 0.f);
        if (e >= 0) v = gx4[(size_t)e * 64 + j];
        *(float4*)&sX[row * XS + 4 * j] = v;
    }
    __syncthreads();

    const float4* Ab = g_Afrag + (size_t)(r * 2 + nh) * AFRAG_PER_NH;

    float acc[2][16][4];
    #pragma unroll
    for (int a = 0; a < 2; a++)
        #pragma unroll
        for (int b = 0; b < 16; b++)
            #pragma unroll
            for (int cc = 0; cc < 4; cc++) acc[a][b][cc] = 0.f;

    for (int ks = 0; ks < 32; ks++) {
        // A frags: warp covers mtiles w*2, w*2+1
        uint32_t ahi[2][4], alo[2][4];
        #pragma unroll
        for (int mt = 0; mt < 2; mt++) {
            float4 h4 = Ab[((ks * 16 + (w * 2 + mt)) * 2 + 0) * 32 + lane];
            float4 l4 = Ab[((ks * 16 + (w * 2 + mt)) * 2 + 1) * 32 + lane];
            ahi[mt][0] = __float_as_uint(h4.x); ahi[mt][1] = __float_as_uint(h4.y);
            ahi[mt][2] = __float_as_uint(h4.z); ahi[mt][3] = __float_as_uint(h4.w);
            alo[mt][0] = __float_as_uint(l4.x); alo[mt][1] = __float_as_uint(l4.y);
            alo[mt][2] = __float_as_uint(l4.z); alo[mt][3] = __float_as_uint(l4.w);
        }
        #pragma unroll
        for (int nt = 0; nt < 16; nt++) {
            // B frag: B[k][edge] = X[edge][k]; b0 k=tig, b1 k=tig+4; edge = nt*8+g
            const float* xr = &sX[(nt * 8 + g) * XS + ks * 8 + tig];
            float b0f = xr[0], b1f = xr[4];
            float b0h = tf32hi(b0f), b1h = tf32hi(b1f);
            uint32_t bh0 = __float_as_uint(b0h), bh1 = __float_as_uint(b1h);
            uint32_t bl0 = __float_as_uint(tf32hi(b0f - b0h));
            uint32_t bl1 = __float_as_uint(tf32hi(b1f - b1h));
            #pragma unroll
            for (int mt = 0; mt < 2; mt++) {
                mma8(acc[mt][nt], ahi[mt], bh0, bh1);
                mma8(acc[mt][nt], ahi[mt], bl0, bl1);
                mma8(acc[mt][nt], alo[mt], bh0, bh1);
            }
        }
    }

    // store raw gates to g_y[e][512]
    #pragma unroll
    for (int mt = 0; mt < 2; mt++) {
        int col = nh * 256 + (w * 2 + mt) * 16 + g;
        #pragma unroll
        for (int nt = 0; nt < 16; nt++) {
            int e0 = sEid[nt * 8 + 2 * tig];
            int e1 = sEid[nt * 8 + 2 * tig + 1];
            if (e0 >= 0) {
                g_y[(size_t)e0 * NB + col]     = acc[mt][nt][0];
                g_y[(size_t)e0 * NB + col + 8] = acc[mt][nt][2];
            }
            if (e1 >= 0) {
                g_y[(size_t)e1 * NB + col]     = acc[mt][nt][1];
                g_y[(size_t)e1 * NB + col + 8] = acc[mt][nt][3];
            }
        }
    }
}

// -------- epilogue: GRU nonlinearity + last-edge-wins scatter --------
__global__ void __launch_bounds__(HH)
k_epi(const int* __restrict__ rel, const int* __restrict__ src,
      float* __restrict__ out, int N) {
    int e = blockIdx.x;
    __shared__ int sr, ss, slast;
    if (threadIdx.x == 0) {
        int r = rel[e], s = src[e];
        sr = r; ss = s;
        slast = (g_lastpos[(size_t)r * N + s] == e) ? 1 : 0;
    }
    __syncthreads();
    if (!slast) return;
    int r = sr, col = threadIdx.x;
    float yr = g_y[(size_t)e * NB + col];
    float yz = g_y[(size_t)e * NB + HH + col];
    float yn = g_y[(size_t)e * NB + 2 * HH + col];
    float yh = g_y[(size_t)e * NB + G3 + col];
    float rg = 1.f / (1.f + expf(-(yr + g_bc[r * G3 + col])));
    float zg = 1.f / (1.f + expf(-(yz + g_bc[r * G3 + HH + col])));
    float ng = tanhf(yn + g_bc[r * G3 + 2 * HH + col] + rg * (yh + g_bhn[r * HH + col]));
    float hp = g_x[(size_t)e * HH2 + HH + col];
    out[((size_t)r * N + ss) * HH + col] = (1.f - zg) * ng + zg * hp;
}

// -------- launch --------
extern "C" void kernel_launch(void* const* d_in, const int* in_sizes, int n_in,
                              void* d_out, int out_size) {
    const float* prev  = (const float*)d_in[0];
    const float* encW  = (const float*)d_in[1];
    const float* encb  = (const float*)d_in[2];
    const float* W_ih  = (const float*)d_in[3];
    const float* W_hh  = (const float*)d_in[4];
    const float* b_ih  = (const float*)d_in[5];
    const float* b_hh  = (const float*)d_in[6];
    const int*   src   = (const int*)d_in[7];
    const int*   dst   = (const int*)d_in[8];
    const int*   rel   = (const int*)d_in[9];
    const int*   t_edg = (const int*)d_in[10];
    const int*   ctp   = (n_in > 11) ? (const int*)d_in[11] : nullptr;
    float* out = (float*)d_out;

    int E  = in_sizes[7];
    int b_ih_n = in_sizes[5];                 // R*3H
    int W_hh_n = in_sizes[4];                 // R*3H*H
    int Hd = W_hh_n / b_ih_n;                 // 128
    int Rd = b_ih_n / (3 * Hd);               // 8
    long long prevN = in_sizes[0];
    int Nd = (int)(prevN / ((long long)Rd * Hd));
    int Td = in_sizes[1] / (2 * Rd * Hd);

    // 1) copy prev -> out
    size_t n4 = (size_t)out_size / 4;
    k_copy<<<4736, 256>>>((const float4*)prev, (float4*)out, n4);

    // 2) reset scratch
    int totalLP = Rd * Nd;
    k_init<<<(totalLP + 255) / 256, 256>>>(totalLP);

    // 3) transposed encoder table
    int encN = Rd * Td * Hd;
    k_encT<<<(encN + 255) / 256, 256>>>(encW, encb, Rd, Td);

    // 4) fragment-major tf32 hi/lo weights + biases
    int prepN = Rd * 2 * AFRAG_PER_NH;
    k_prep<<<(prepN + 255) / 256, 256>>>(W_ih, W_hh, b_ih, b_hh, Rd);

    // 5) counts + lastpos
    k_count<<<(E + 255) / 256, 256>>>(rel, src, E, Nd);

    // 6) scan
    k_scan<<<1, 32>>>(Rd);

    // 7) group edges by relation
    k_order<<<(E + 255) / 256, 256>>>(rel, E);

    // 8) build x = [enc + u_j, u_i]
    int bxN = E * Hd;
    k_build_x<<<(bxN + 255) / 256, 256>>>(prev, src, dst, rel, t_edg, ctp, E, Nd, Td);

    // 9) tensor-core GEMM (mma.sync tf32x3) -> raw gates in g_y
    cudaFuncSetAttribute(k_gru_mma, cudaFuncAttributeMaxDynamicSharedMemorySize, SMEM_MMA);
    dim3 grid(Rd, (E + MT_E - 1) / MT_E, 2);
    k_gru_mma<<<grid, TPB, SMEM_MMA>>>();

    // 10) epilogue: nonlinearity + scatter
    k_epi<<<E, HH>>>(rel, src, out, Nd);
}

// round 5
// speedup vs baseline: 1.5039x; 1.1096x over previous
#include <cuda_runtime.h>
#include <cstdint>

typedef unsigned long long ull;

// Problem constants
#define HH   128
#define HH2  256
#define G3   384
#define NB   512          // gate rows: 256 folded r/z + 128 n + 128 hn
#define RMAX 8
#define NMAX 100000
#define EMAX 50000

// mma tile config
#define MT_E   128        // edges per CTA tile
#define TPB    512        // 16 warps, 1 mtile each
#define XS2    68         // smem X chunk row stride (floats); (4g+tig) mod 32 unique
// A-frag global layout: [r][nhalf][ks=32][mt=16][hl=2][lane=32] float4
#define AFRAG_PER_NH 32768   // 32*16*2*32 float4s

// -------- scratch (device globals; no runtime allocation) --------
__device__ int   g_lastpos[RMAX * NMAX];
__device__ int   g_cnt[RMAX];
__device__ int   g_off[RMAX + 1];
__device__ int   g_cursor[RMAX];
__device__ int   g_order[EMAX];
__device__ float g_x[(size_t)EMAX * HH2];
__device__ float g_y[(size_t)EMAX * NB];
__device__ float g_encT[RMAX * 64 * HH];                     // [r][t][h], T<=64
__device__ float4 g_Afrag[(size_t)RMAX * 2 * AFRAG_PER_NH];  // frag-major weights (tf32 hi/lo)
__device__ float g_bc[RMAX * G3];                            // b_ih (+ b_hh for r,z)
__device__ float g_bhn[RMAX * HH];                           // b_hh n-gate

// -------- helpers --------
__device__ __forceinline__ float tf32hi(float v) {
    uint32_t b;
    asm("cvt.rna.tf32.f32 %0, %1;" : "=r"(b) : "f"(v));
    return __uint_as_float(b);
}
__device__ __forceinline__ void mma8(float* c, const uint32_t* a, uint32_t b0, uint32_t b1) {
    asm volatile(
        "mma.sync.aligned.m16n8k8.row.col.f32.tf32.tf32.f32 "
        "{%0,%1,%2,%3}, {%4,%5,%6,%7}, {%8,%9}, {%0,%1,%2,%3};"
        : "+f"(c[0]), "+f"(c[1]), "+f"(c[2]), "+f"(c[3])
        : "r"(a[0]), "r"(a[1]), "r"(a[2]), "r"(a[3]), "r"(b0), "r"(b1));
}

// -------- small kernels --------
__global__ void k_copy(const float4* __restrict__ in, float4* __restrict__ out, size_t n4) {
    size_t i = (size_t)blockIdx.x * blockDim.x + threadIdx.x;
    size_t stride = (size_t)gridDim.x * blockDim.x;
    for (; i < n4; i += stride) out[i] = in[i];
}

__global__ void k_init(int total) {
    int i = blockIdx.x * blockDim.x + threadIdx.x;
    int stride = gridDim.x * blockDim.x;
    for (; i < total; i += stride) g_lastpos[i] = -1;
    if (blockIdx.x == 0 && threadIdx.x < RMAX) {
        g_cnt[threadIdx.x] = 0;
        g_cursor[threadIdx.x] = 0;
    }
}

__global__ void k_encT(const float* __restrict__ encW, const float* __restrict__ encb,
                       int R, int T) {
    int i = blockIdx.x * blockDim.x + threadIdx.x;
    int total = R * T * HH;
    if (i >= total) return;
    int h = i % HH;
    int t = (i / HH) % T;
    int r = i / (HH * T);
    g_encT[i] = encW[(size_t)(r * HH + h) * T + t] + encb[r * HH + h];
}

// Build fragment-major tf32 hi/lo weight tensor + combined biases.
__global__ void k_prep(const float* __restrict__ W_ih, const float* __restrict__ W_hh,
                       const float* __restrict__ b_ih, const float* __restrict__ b_hh,
                       int R) {
    int i = blockIdx.x * blockDim.x + threadIdx.x;
    int total = R * 2 * AFRAG_PER_NH;
    if (i < total) {
        int lane = i & 31;
        int hl   = (i >> 5) & 1;
        int mt   = (i >> 6) & 15;
        int ks   = (i >> 10) & 31;
        int nh   = (i >> 15) & 1;
        int r    = i >> 16;
        int g    = lane >> 2;
        int tig  = lane & 3;
        float4 v4;
        float* vp = (float*)&v4;
        #pragma unroll
        for (int j = 0; j < 4; j++) {
            int m_local = mt * 16 + (j & 1) * 8 + g;   // 0..255
            int k       = ks * 8 + (j >> 1) * 4 + tig; // 0..255
            int row = nh * 256 + m_local;              // 0..511
            float v;
            if (row < 2 * HH) {
                v = W_ih[((size_t)r * G3 + row) * HH2 + k];
                if (k >= HH) v += W_hh[((size_t)r * G3 + row) * HH + (k - HH)];
            } else if (row < G3) {
                v = W_ih[((size_t)r * G3 + row) * HH2 + k];
            } else {
                int col = row - G3;
                v = (k >= HH) ? W_hh[((size_t)r * G3 + 2 * HH + col) * HH + (k - HH)] : 0.f;
            }
            float hi = tf32hi(v);
            vp[j] = hl ? (v - hi) : hi;   // lo fed raw (HW truncates, err ~2^-22)
        }
        g_Afrag[i] = v4;
    }
    if (i < R * G3) {
        int col3 = i % G3;
        int r    = i / G3;
        int g    = col3 >> 7;
        g_bc[i] = b_ih[i] + ((g < 2) ? b_hh[i] : 0.f);
        if (g == 2) g_bhn[r * HH + (col3 & 127)] = b_hh[i];
    }
}

__global__ void k_count(const int* __restrict__ rel, const int* __restrict__ src,
                        int E, int N) {
    __shared__ int sc[RMAX];
    if (threadIdx.x < RMAX) sc[threadIdx.x] = 0;
    __syncthreads();
    int i = blockIdx.x * blockDim.x + threadIdx.x;
    if (i < E) {
        int r = rel[i];
        atomicMax(&g_lastpos[(size_t)r * N + src[i]], i);
        atomicAdd(&sc[r], 1);
    }
    __syncthreads();
    if (threadIdx.x < RMAX && sc[threadIdx.x])
        atomicAdd(&g_cnt[threadIdx.x], sc[threadIdx.x]);
}

__global__ void k_scan(int R) {
    if (threadIdx.x == 0) {
        int acc = 0;
        for (int r = 0; r < R; r++) {
            g_off[r] = acc;
            g_cursor[r] = acc;
            acc += g_cnt[r];
        }
        g_off[R] = acc;
    }
}

__global__ void k_order(const int* __restrict__ rel, int E) {
    __shared__ int sc[RMAX], sbase[RMAX];
    if (threadIdx.x < RMAX) sc[threadIdx.x] = 0;
    __syncthreads();
    int i = blockIdx.x * blockDim.x + threadIdx.x;
    int r = 0, pos = 0;
    bool valid = (i < E);
    if (valid) {
        r = rel[i];
        pos = atomicAdd(&sc[r], 1);
    }
    __syncthreads();
    if (threadIdx.x < RMAX && sc[threadIdx.x])
        sbase[threadIdx.x] = atomicAdd(&g_cursor[threadIdx.x], sc[threadIdx.x]);
    __syncthreads();
    if (valid) g_order[sbase[r] + pos] = i;
}

__global__ void k_build_x(const float* __restrict__ prev, const int* __restrict__ src,
                          const int* __restrict__ dst, const int* __restrict__ rel,
                          const int* __restrict__ t_edge, const int* __restrict__ ctp,
                          int E, int N, int T) {
    int i = blockIdx.x * blockDim.x + threadIdx.x;
    if (i >= E * HH) return;
    int e = i >> 7;
    int h = i & (HH - 1);
    int r = rel[e];
    int ct = ctp ? ctp[0] : 100;
    int b = min(ct - t_edge[e], T - 1);
    float enc = g_encT[(r * T + b) * HH + h];
    float uj = prev[((size_t)r * N + dst[e]) * HH + h];
    float ui = prev[((size_t)r * N + src[e]) * HH + h];
    g_x[(size_t)e * HH2 + h]      = enc + uj;
    g_x[(size_t)e * HH2 + HH + h] = ui;
}

// -------- tensor-core GEMM: Y[e, nh*256 .. +256] = X[e,:] . W^T (3xTF32) --------
// smem: sX [128][XS2] floats + sBf [8*16*32] float4 + sEid[128]
#define SX_F    (MT_E * XS2)
#define SBF_F4  (8 * 16 * 32)
#define SMEM_MMA (SX_F * 4 + SBF_F4 * 16 + MT_E * 4)

__global__ void __launch_bounds__(TPB, 1)
k_gru_mma() {
    int r  = blockIdx.x;
    int nh = blockIdx.z;
    int begin = g_off[r], end = g_off[r + 1];
    int base = begin + blockIdx.y * MT_E;
    if (base >= end) return;
    int mE = min(MT_E, end - base);
    int tid = threadIdx.x;
    int w = tid >> 5, lane = tid & 31;
    int g = lane >> 2, tig = lane & 3;

    extern __shared__ float sm[];
    float*  sX   = sm;                         // [m][k-chunk] stride XS2
    float4* sBf  = (float4*)(sm + SX_F);       // [ksl][nt][lane]
    int*    sEid = (int*)(sBf + SBF_F4);

    if (tid < MT_E)
        sEid[tid] = (tid < mE) ? g_order[base + tid] : -1;

    const float4* gx4 = (const float4*)g_x;
    const float4* Ab = g_Afrag + (size_t)(r * 2 + nh) * AFRAG_PER_NH;

    float acc[16][4];
    #pragma unroll
    for (int b = 0; b < 16; b++)
        #pragma unroll
        for (int cc = 0; cc < 4; cc++) acc[b][cc] = 0.f;

    for (int kc = 0; kc < 4; kc++) {
        __syncthreads();   // protect sX/sBf from previous iteration readers
        // ---- load X chunk [128 edges][64 k] (coalesced float4) ----
        #pragma unroll
        for (int it = 0; it < 4; it++) {
            int s = tid + it * TPB;            // 0..2047
            int row = s >> 4, j = s & 15;
            int e = sEid[row];
            float4 v = make_float4(0.f, 0.f, 0.f, 0.f);
            if (e >= 0) v = gx4[(size_t)e * 64 + kc * 16 + j];
            *(float4*)&sX[row * XS2 + 4 * j] = v;
        }
        __syncthreads();
        // ---- build B fragments once: sBf[ksl][nt][lane] = (b0h,b1h,b0l,b1l) ----
        #pragma unroll
        for (int it = 0; it < 8; it++) {
            int s = tid + it * TPB;            // 0..4095
            int l2  = s & 31;
            int nt2 = (s >> 5) & 15;
            int ks2 = s >> 9;
            const float* xr = &sX[(nt2 * 8 + (l2 >> 2)) * XS2 + ks2 * 8 + (l2 & 3)];
            float b0 = xr[0], b1 = xr[4];
            float b0h = tf32hi(b0), b1h = tf32hi(b1);
            sBf[s] = make_float4(b0h, b1h, b0 - b0h, b1 - b1h);
        }
        __syncthreads();
        // ---- compute: warp w owns mtile w ----
        #pragma unroll
        for (int ksl = 0; ksl < 8; ksl++) {
            int ks = kc * 8 + ksl;
            const float4* Ap = Ab + ((size_t)(ks * 16 + w) * 2) * 32 + lane;
            float4 h4 = Ap[0];
            float4 l4 = Ap[32];
            uint32_t ahi[4] = {__float_as_uint(h4.x), __float_as_uint(h4.y),
                               __float_as_uint(h4.z), __float_as_uint(h4.w)};
            uint32_t alo[4] = {__float_as_uint(l4.x), __float_as_uint(l4.y),
                               __float_as_uint(l4.z), __float_as_uint(l4.w)};
            #pragma unroll
            for (int nt = 0; nt < 16; nt++) {
                float4 bf = sBf[(ksl * 16 + nt) * 32 + lane];
                uint32_t bh0 = __float_as_uint(bf.x), bh1 = __float_as_uint(bf.y);
                uint32_t bl0 = __float_as_uint(bf.z), bl1 = __float_as_uint(bf.w);
                mma8(acc[nt], ahi, bh0, bh1);
                mma8(acc[nt], ahi, bl0, bl1);
                mma8(acc[nt], alo, bh0, bh1);
            }
        }
    }

    // ---- store raw gates to g_y[e][512] ----
    int col = nh * 256 + w * 16 + g;
    #pragma unroll
    for (int nt = 0; nt < 16; nt++) {
        int e0 = sEid[nt * 8 + 2 * tig];
        int e1 = sEid[nt * 8 + 2 * tig + 1];
        if (e0 >= 0) {
            g_y[(size_t)e0 * NB + col]     = acc[nt][0];
            g_y[(size_t)e0 * NB + col + 8] = acc[nt][2];
        }
        if (e1 >= 0) {
            g_y[(size_t)e1 * NB + col]     = acc[nt][1];
            g_y[(size_t)e1 * NB + col + 8] = acc[nt][3];
        }
    }
}

// -------- epilogue: GRU nonlinearity + last-edge-wins scatter --------
__global__ void __launch_bounds__(HH)
k_epi(const int* __restrict__ rel, const int* __restrict__ src,
      float* __restrict__ out, int N) {
    int e = blockIdx.x;
    __shared__ int sr, ss, slast;
    if (threadIdx.x == 0) {
        int r = rel[e], s = src[e];
        sr = r; ss = s;
        slast = (g_lastpos[(size_t)r * N + s] == e) ? 1 : 0;
    }
    __syncthreads();
    if (!slast) return;
    int r = sr, col = threadIdx.x;
    float yr = g_y[(size_t)e * NB + col];
    float yz = g_y[(size_t)e * NB + HH + col];
    float yn = g_y[(size_t)e * NB + 2 * HH + col];
    float yh = g_y[(size_t)e * NB + G3 + col];
    float rg = 1.f / (1.f + expf(-(yr + g_bc[r * G3 + col])));
    float zg = 1.f / (1.f + expf(-(yz + g_bc[r * G3 + HH + col])));
    float ng = tanhf(yn + g_bc[r * G3 + 2 * HH + col] + rg * (yh + g_bhn[r * HH + col]));
    float hp = g_x[(size_t)e * HH2 + HH + col];
    out[((size_t)r * N + ss) * HH + col] = (1.f - zg) * ng + zg * hp;
}

// -------- launch --------
extern "C" void kernel_launch(void* const* d_in, const int* in_sizes, int n_in,
                              void* d_out, int out_size) {
    const float* prev  = (const float*)d_in[0];
    const float* encW  = (const float*)d_in[1];
    const float* encb  = (const float*)d_in[2];
    const float* W_ih  = (const float*)d_in[3];
    const float* W_hh  = (const float*)d_in[4];
    const float* b_ih  = (const float*)d_in[5];
    const float* b_hh  = (const float*)d_in[6];
    const int*   src   = (const int*)d_in[7];
    const int*   dst   = (const int*)d_in[8];
    const int*   rel   = (const int*)d_in[9];
    const int*   t_edg = (const int*)d_in[10];
    const int*   ctp   = (n_in > 11) ? (const int*)d_in[11] : nullptr;
    float* out = (float*)d_out;

    int E  = in_sizes[7];
    int b_ih_n = in_sizes[5];                 // R*3H
    int W_hh_n = in_sizes[4];                 // R*3H*H
    int Hd = W_hh_n / b_ih_n;                 // 128
    int Rd = b_ih_n / (3 * Hd);               // 8
    long long prevN = in_sizes[0];
    int Nd = (int)(prevN / ((long long)Rd * Hd));
    int Td = in_sizes[1] / (2 * Rd * Hd);

    // 1) copy prev -> out
    size_t n4 = (size_t)out_size / 4;
    k_copy<<<4736, 256>>>((const float4*)prev, (float4*)out, n4);

    // 2) reset scratch
    int totalLP = Rd * Nd;
    k_init<<<(totalLP + 255) / 256, 256>>>(totalLP);

    // 3) transposed encoder table
    int encN = Rd * Td * Hd;
    k_encT<<<(encN + 255) / 256, 256>>>(encW, encb, Rd, Td);

    // 4) fragment-major tf32 hi/lo weights + biases
    int prepN = Rd * 2 * AFRAG_PER_NH;
    k_prep<<<(prepN + 255) / 256, 256>>>(W_ih, W_hh, b_ih, b_hh, Rd);

    // 5) counts + lastpos
    k_count<<<(E + 255) / 256, 256>>>(rel, src, E, Nd);

    // 6) scan
    k_scan<<<1, 32>>>(Rd);

    // 7) group edges by relation
    k_order<<<(E + 255) / 256, 256>>>(rel, E);

    // 8) build x = [enc + u_j, u_i]
    int bxN = E * Hd;
    k_build_x<<<(bxN + 255) / 256, 256>>>(prev, src, dst, rel, t_edg, ctp, E, Nd, Td);

    // 9) tensor-core GEMM (mma.sync tf32x3) -> raw gates in g_y
    cudaFuncSetAttribute(k_gru_mma, cudaFuncAttributeMaxDynamicSharedMemorySize, SMEM_MMA);
    dim3 grid(Rd, (E + MT_E - 1) / MT_E, 2);
    k_gru_mma<<<grid, TPB, SMEM_MMA>>>();

    // 10) epilogue: nonlinearity + scatter
    k_epi<<<E, HH>>>(rel, src, out, Nd);
}

// round 6
// speedup vs baseline: 1.5044x; 1.0003x over previous
#include <cuda_runtime.h>
#include <cstdint>

typedef unsigned long long ull;

// Problem constants
#define HH   128
#define HH2  256
#define G3   384
#define NB   512          // gate rows: 256 folded r/z + 128 n + 128 hn
#define RMAX 8
#define NMAX 100000
#define EMAX 50000

// mma tile config
#define MT_E   128        // edges per CTA tile
#define TPB    512        // 16 warps, 1 mtile each
#define XS2    68         // smem X chunk row stride (floats); (4g+tig) mod 32 unique
// A-frag global layout: [r][nhalf][ks=32][mt=16][hl=2][lane=32] float4
#define AFRAG_PER_NH 32768   // 32*16*2*32 float4s

// -------- scratch (device globals; no runtime allocation) --------
__device__ int   g_lastpos[RMAX * NMAX];
__device__ int   g_cnt[RMAX];
__device__ int   g_off[RMAX + 1];
__device__ int   g_cursor[RMAX];
__device__ int   g_order[EMAX];
__device__ float g_x[(size_t)EMAX * HH2];
__device__ float g_y[(size_t)EMAX * NB];
__device__ float g_encT[RMAX * 64 * HH];                     // [r][t][h], T<=64
__device__ float4 g_Afrag[(size_t)RMAX * 2 * AFRAG_PER_NH];  // frag-major weights (tf32 hi/lo)
__device__ float g_bc[RMAX * G3];                            // b_ih (+ b_hh for r,z)
__device__ float g_bhn[RMAX * HH];                           // b_hh n-gate

// -------- helpers --------
__device__ __forceinline__ float tf32hi(float v) {
    uint32_t b;
    asm("cvt.rna.tf32.f32 %0, %1;" : "=r"(b) : "f"(v));
    return __uint_as_float(b);
}
__device__ __forceinline__ void mma8(float* c, const uint32_t* a, uint32_t b0, uint32_t b1) {
    asm volatile(
        "mma.sync.aligned.m16n8k8.row.col.f32.tf32.tf32.f32 "
        "{%0,%1,%2,%3}, {%4,%5,%6,%7}, {%8,%9}, {%0,%1,%2,%3};"
        : "+f"(c[0]), "+f"(c[1]), "+f"(c[2]), "+f"(c[3])
        : "r"(a[0]), "r"(a[1]), "r"(a[2]), "r"(a[3]), "r"(b0), "r"(b1));
}

// -------- small kernels --------
__global__ void k_copy(const float4* __restrict__ in, float4* __restrict__ out, size_t n4) {
    size_t i = (size_t)blockIdx.x * blockDim.x + threadIdx.x;
    size_t stride = (size_t)gridDim.x * blockDim.x;
    for (; i < n4; i += stride) out[i] = in[i];
}

__global__ void k_init(int total) {
    int i = blockIdx.x * blockDim.x + threadIdx.x;
    int stride = gridDim.x * blockDim.x;
    for (; i < total; i += stride) g_lastpos[i] = -1;
    if (blockIdx.x == 0 && threadIdx.x < RMAX) {
        g_cnt[threadIdx.x] = 0;
        g_cursor[threadIdx.x] = 0;
    }
}

__global__ void k_encT(const float* __restrict__ encW, const float* __restrict__ encb,
                       int R, int T) {
    int i = blockIdx.x * blockDim.x + threadIdx.x;
    int total = R * T * HH;
    if (i >= total) return;
    int h = i % HH;
    int t = (i / HH) % T;
    int r = i / (HH * T);
    g_encT[i] = encW[(size_t)(r * HH + h) * T + t] + encb[r * HH + h];
}

// Build fragment-major tf32 hi/lo weight tensor + combined biases.
__global__ void k_prep(const float* __restrict__ W_ih, const float* __restrict__ W_hh,
                       const float* __restrict__ b_ih, const float* __restrict__ b_hh,
                       int R) {
    int i = blockIdx.x * blockDim.x + threadIdx.x;
    int total = R * 2 * AFRAG_PER_NH;
    if (i < total) {
        int lane = i & 31;
        int hl   = (i >> 5) & 1;
        int mt   = (i >> 6) & 15;
        int ks   = (i >> 10) & 31;
        int nh   = (i >> 15) & 1;
        int r    = i >> 16;
        int g    = lane >> 2;
        int tig  = lane & 3;
        float4 v4;
        float* vp = (float*)&v4;
        #pragma unroll
        for (int j = 0; j < 4; j++) {
            int m_local = mt * 16 + (j & 1) * 8 + g;   // 0..255
            int k       = ks * 8 + (j >> 1) * 4 + tig; // 0..255
            int row = nh * 256 + m_local;              // 0..511
            float v;
            if (row < 2 * HH) {
                v = W_ih[((size_t)r * G3 + row) * HH2 + k];
                if (k >= HH) v += W_hh[((size_t)r * G3 + row) * HH + (k - HH)];
            } else if (row < G3) {
                v = W_ih[((size_t)r * G3 + row) * HH2 + k];
            } else {
                int col = row - G3;
                v = (k >= HH) ? W_hh[((size_t)r * G3 + 2 * HH + col) * HH + (k - HH)] : 0.f;
            }
            float hi = tf32hi(v);
            vp[j] = hl ? (v - hi) : hi;   // lo fed raw (HW truncates, err ~2^-22)
        }
        g_Afrag[i] = v4;
    }
    if (i < R * G3) {
        int col3 = i % G3;
        int r    = i / G3;
        int g    = col3 >> 7;
        g_bc[i] = b_ih[i] + ((g < 2) ? b_hh[i] : 0.f);
        if (g == 2) g_bhn[r * HH + (col3 & 127)] = b_hh[i];
    }
}

__global__ void k_count(const int* __restrict__ rel, const int* __restrict__ src,
                        int E, int N) {
    __shared__ int sc[RMAX];
    if (threadIdx.x < RMAX) sc[threadIdx.x] = 0;
    __syncthreads();
    int i = blockIdx.x * blockDim.x + threadIdx.x;
    if (i < E) {
        int r = rel[i];
        atomicMax(&g_lastpos[(size_t)r * N + src[i]], i);
        atomicAdd(&sc[r], 1);
    }
    __syncthreads();
    if (threadIdx.x < RMAX && sc[threadIdx.x])
        atomicAdd(&g_cnt[threadIdx.x], sc[threadIdx.x]);
}

__global__ void k_scan(int R) {
    if (threadIdx.x == 0) {
        int acc = 0;
        for (int r = 0; r < R; r++) {
            g_off[r] = acc;
            g_cursor[r] = acc;
            acc += g_cnt[r];
        }
        g_off[R] = acc;
    }
}

__global__ void k_order(const int* __restrict__ rel, int E) {
    __shared__ int sc[RMAX], sbase[RMAX];
    if (threadIdx.x < RMAX) sc[threadIdx.x] = 0;
    __syncthreads();
    int i = blockIdx.x * blockDim.x + threadIdx.x;
    int r = 0, pos = 0;
    bool valid = (i < E);
    if (valid) {
        r = rel[i];
        pos = atomicAdd(&sc[r], 1);
    }
    __syncthreads();
    if (threadIdx.x < RMAX && sc[threadIdx.x])
        sbase[threadIdx.x] = atomicAdd(&g_cursor[threadIdx.x], sc[threadIdx.x]);
    __syncthreads();
    if (valid) g_order[sbase[r] + pos] = i;
}

__global__ void k_build_x(const float* __restrict__ prev, const int* __restrict__ src,
                          const int* __restrict__ dst, const int* __restrict__ rel,
                          const int* __restrict__ t_edge, const int* __restrict__ ctp,
                          int E, int N, int T) {
    int i = blockIdx.x * blockDim.x + threadIdx.x;
    if (i >= E * HH) return;
    int e = i >> 7;
    int h = i & (HH - 1);
    int r = rel[e];
    int ct = ctp ? ctp[0] : 100;
    int b = min(ct - t_edge[e], T - 1);
    float enc = g_encT[(r * T + b) * HH + h];
    float uj = prev[((size_t)r * N + dst[e]) * HH + h];
    float ui = prev[((size_t)r * N + src[e]) * HH + h];
    g_x[(size_t)e * HH2 + h]      = enc + uj;
    g_x[(size_t)e * HH2 + HH + h] = ui;
}

// -------- tensor-core GEMM: Y[e, nh*256 .. +256] = X[e,:] . W^T (3xTF32) --------
// smem: sX [128][XS2] floats + sBf [8*16*32] float4 + sEid[128]
#define SX_F    (MT_E * XS2)
#define SBF_F4  (8 * 16 * 32)
#define SMEM_MMA (SX_F * 4 + SBF_F4 * 16 + MT_E * 4)

__global__ void __launch_bounds__(TPB, 1)
k_gru_mma() {
    int r  = blockIdx.x;
    int nh = blockIdx.z;
    int begin = g_off[r], end = g_off[r + 1];
    int base = begin + blockIdx.y * MT_E;
    if (base >= end) return;
    int mE = min(MT_E, end - base);
    int tid = threadIdx.x;
    int w = tid >> 5, lane = tid & 31;
    int g = lane >> 2, tig = lane & 3;

    extern __shared__ float sm[];
    float*  sX   = sm;                         // [m][k-chunk] stride XS2
    float4* sBf  = (float4*)(sm + SX_F);       // [ksl][nt][lane]
    int*    sEid = (int*)(sBf + SBF_F4);

    if (tid < MT_E)
        sEid[tid] = (tid < mE) ? g_order[base + tid] : -1;

    const float4* gx4 = (const float4*)g_x;
    const float4* Ab = g_Afrag + (size_t)(r * 2 + nh) * AFRAG_PER_NH;

    float acc[16][4];
    #pragma unroll
    for (int b = 0; b < 16; b++)
        #pragma unroll
        for (int cc = 0; cc < 4; cc++) acc[b][cc] = 0.f;

    for (int kc = 0; kc < 4; kc++) {
        __syncthreads();   // protect sX/sBf from previous iteration readers
        // ---- load X chunk [128 edges][64 k] (coalesced float4) ----
        #pragma unroll
        for (int it = 0; it < 4; it++) {
            int s = tid + it * TPB;            // 0..2047
            int row = s >> 4, j = s & 15;
            int e = sEid[row];
            float4 v = make_float4(0.f, 0.f, 0.f, 0.f);
            if (e >= 0) v = gx4[(size_t)e * 64 + kc * 16 + j];
            *(float4*)&sX[row * XS2 + 4 * j] = v;
        }
        __syncthreads();
        // ---- build B fragments once: sBf[ksl][nt][lane] = (b0h,b1h,b0l,b1l) ----
        #pragma unroll
        for (int it = 0; it < 8; it++) {
            int s = tid + it * TPB;            // 0..4095
            int l2  = s & 31;
            int nt2 = (s >> 5) & 15;
            int ks2 = s >> 9;
            const float* xr = &sX[(nt2 * 8 + (l2 >> 2)) * XS2 + ks2 * 8 + (l2 & 3)];
            float b0 = xr[0], b1 = xr[4];
            float b0h = tf32hi(b0), b1h = tf32hi(b1);
            sBf[s] = make_float4(b0h, b1h, b0 - b0h, b1 - b1h);
        }
        __syncthreads();
        // ---- compute: warp w owns mtile w ----
        #pragma unroll
        for (int ksl = 0; ksl < 8; ksl++) {
            int ks = kc * 8 + ksl;
            const float4* Ap = Ab + ((size_t)(ks * 16 + w) * 2) * 32 + lane;
            float4 h4 = Ap[0];
            float4 l4 = Ap[32];
            uint32_t ahi[4] = {__float_as_uint(h4.x), __float_as_uint(h4.y),
                               __float_as_uint(h4.z), __float_as_uint(h4.w)};
            uint32_t alo[4] = {__float_as_uint(l4.x), __float_as_uint(l4.y),
                               __float_as_uint(l4.z), __float_as_uint(l4.w)};
            #pragma unroll
            for (int nt = 0; nt < 16; nt++) {
                float4 bf = sBf[(ksl * 16 + nt) * 32 + lane];
                uint32_t bh0 = __float_as_uint(bf.x), bh1 = __float_as_uint(bf.y);
                uint32_t bl0 = __float_as_uint(bf.z), bl1 = __float_as_uint(bf.w);
                mma8(acc[nt], ahi, bh0, bh1);
                mma8(acc[nt], ahi, bl0, bl1);
                mma8(acc[nt], alo, bh0, bh1);
            }
        }
    }

    // ---- store raw gates to g_y[e][512] ----
    int col = nh * 256 + w * 16 + g;
    #pragma unroll
    for (int nt = 0; nt < 16; nt++) {
        int e0 = sEid[nt * 8 + 2 * tig];
        int e1 = sEid[nt * 8 + 2 * tig + 1];
        if (e0 >= 0) {
            g_y[(size_t)e0 * NB + col]     = acc[nt][0];
            g_y[(size_t)e0 * NB + col + 8] = acc[nt][2];
        }
        if (e1 >= 0) {
            g_y[(size_t)e1 * NB + col]     = acc[nt][1];
            g_y[(size_t)e1 * NB + col + 8] = acc[nt][3];
        }
    }
}

// -------- epilogue: GRU nonlinearity + last-edge-wins scatter --------
__global__ void __launch_bounds__(HH)
k_epi(const int* __restrict__ rel, const int* __restrict__ src,
      float* __restrict__ out, int N) {
    int e = blockIdx.x;
    __shared__ int sr, ss, slast;
    if (threadIdx.x == 0) {
        int r = rel[e], s = src[e];
        sr = r; ss = s;
        slast = (g_lastpos[(size_t)r * N + s] == e) ? 1 : 0;
    }
    __syncthreads();
    if (!slast) return;
    int r = sr, col = threadIdx.x;
    float yr = g_y[(size_t)e * NB + col];
    float yz = g_y[(size_t)e * NB + HH + col];
    float yn = g_y[(size_t)e * NB + 2 * HH + col];
    float yh = g_y[(size_t)e * NB + G3 + col];
    float rg = 1.f / (1.f + expf(-(yr + g_bc[r * G3 + col])));
    float zg = 1.f / (1.f + expf(-(yz + g_bc[r * G3 + HH + col])));
    float ng = tanhf(yn + g_bc[r * G3 + 2 * HH + col] + rg * (yh + g_bhn[r * HH + col]));
    float hp = g_x[(size_t)e * HH2 + HH + col];
    out[((size_t)r * N + ss) * HH + col] = (1.f - zg) * ng + zg * hp;
}

// -------- launch --------
extern "C" void kernel_launch(void* const* d_in, const int* in_sizes, int n_in,
                              void* d_out, int out_size) {
    const float* prev  = (const float*)d_in[0];
    const float* encW  = (const float*)d_in[1];
    const float* encb  = (const float*)d_in[2];
    const float* W_ih  = (const float*)d_in[3];
    const float* W_hh  = (const float*)d_in[4];
    const float* b_ih  = (const float*)d_in[5];
    const float* b_hh  = (const float*)d_in[6];
    const int*   src   = (const int*)d_in[7];
    const int*   dst   = (const int*)d_in[8];
    const int*   rel   = (const int*)d_in[9];
    const int*   t_edg = (const int*)d_in[10];
    const int*   ctp   = (n_in > 11) ? (const int*)d_in[11] : nullptr;
    float* out = (float*)d_out;

    int E  = in_sizes[7];
    int b_ih_n = in_sizes[5];                 // R*3H
    int W_hh_n = in_sizes[4];                 // R*3H*H
    int Hd = W_hh_n / b_ih_n;                 // 128
    int Rd = b_ih_n / (3 * Hd);               // 8
    long long prevN = in_sizes[0];
    int Nd = (int)(prevN / ((long long)Rd * Hd));
    int Td = in_sizes[1] / (2 * Rd * Hd);

    // 1) copy prev -> out
    size_t n4 = (size_t)out_size / 4;
    k_copy<<<4736, 256>>>((const float4*)prev, (float4*)out, n4);

    // 2) reset scratch
    int totalLP = Rd * Nd;
    k_init<<<(totalLP + 255) / 256, 256>>>(totalLP);

    // 3) transposed encoder table
    int encN = Rd * Td * Hd;
    k_encT<<<(encN + 255) / 256, 256>>>(encW, encb, Rd, Td);

    // 4) fragment-major tf32 hi/lo weights + biases
    int prepN = Rd * 2 * AFRAG_PER_NH;
    k_prep<<<(prepN + 255) / 256, 256>>>(W_ih, W_hh, b_ih, b_hh, Rd);

    // 5) counts + lastpos
    k_count<<<(E + 255) / 256, 256>>>(rel, src, E, Nd);

    // 6) scan
    k_scan<<<1, 32>>>(Rd);

    // 7) group edges by relation
    k_order<<<(E + 255) / 256, 256>>>(rel, E);

    // 8) build x = [enc + u_j, u_i]
    int bxN = E * Hd;
    k_build_x<<<(bxN + 255) / 256, 256>>>(prev, src, dst, rel, t_edg, ctp, E, Nd, Td);

    // 9) tensor-core GEMM (mma.sync tf32x3) -> raw gates in g_y
    cudaFuncSetAttribute(k_gru_mma, cudaFuncAttributeMaxDynamicSharedMemorySize, SMEM_MMA);
    dim3 grid(Rd, (E + MT_E - 1) / MT_E, 2);
    k_gru_mma<<<grid, TPB, SMEM_MMA>>>();

    // 10) epilogue: nonlinearity + scatter
    k_epi<<<E, HH>>>(rel, src, out, Nd);
}

// round 9
// speedup vs baseline: 1.8766x; 1.2474x over previous
#include <cuda_runtime.h>
#include <cuda_bf16.h>
#include <cstdint>

typedef unsigned long long ull;

// Problem constants
#define HH   128
#define HH2  256
#define G3   384
#define NB   512          // gate rows: 256 folded r/z + 128 n + 128 hn
#define RMAX 8
#define NMAX 100000
#define EMAX 50000

// mma tile config
#define MT_E   128        // edges per CTA tile
#define TPB    512        // 16 warps, 1 mtile each
#define XS2    68         // smem X chunk row stride (floats)
// A-frag global layout: [r][nhalf][ks16=16][mt=16][hl=2][lane=32] uint4 (bf16x2 x4)
#define AFRAG_PER_NH 16384

// -------- scratch (device globals; no runtime allocation) --------
__device__ int   g_lastpos[RMAX * NMAX];
__device__ int   g_cnt[RMAX];
__device__ int   g_off[RMAX + 1];
__device__ int   g_cursor[RMAX];
__device__ int   g_order[EMAX];
__device__ float g_x[(size_t)EMAX * HH2];
__device__ float g_y[(size_t)EMAX * NB];
__device__ float g_encT[RMAX * 64 * HH];                    // [r][t][h], T<=64
__device__ uint4 g_Afrag[(size_t)RMAX * 2 * AFRAG_PER_NH];  // bf16 hi/lo A fragments
__device__ float g_bc[RMAX * G3];                           // b_ih (+ b_hh for r,z)
__device__ float g_bhn[RMAX * HH];                          // b_hh n-gate

// -------- helpers --------
__device__ __forceinline__ uint32_t pack_bf16x2(float lo, float hi) {
    uint32_t d;
    asm("cvt.rn.bf16x2.f32 %0, %1, %2;" : "=r"(d) : "f"(hi), "f"(lo));
    return d;
}
__device__ __forceinline__ float bf16rt(float v) {   // value rounded to bf16, back in f32
    return __bfloat162float(__float2bfloat16(v));
}
__device__ __forceinline__ void mma16(float* c, const uint32_t* a, uint32_t b0, uint32_t b1) {
    asm volatile(
        "mma.sync.aligned.m16n8k16.row.col.f32.bf16.bf16.f32 "
        "{%0,%1,%2,%3}, {%4,%5,%6,%7}, {%8,%9}, {%0,%1,%2,%3};"
        : "+f"(c[0]), "+f"(c[1]), "+f"(c[2]), "+f"(c[3])
        : "r"(a[0]), "r"(a[1]), "r"(a[2]), "r"(a[3]), "r"(b0), "r"(b1));
}

// -------- small kernels --------
__global__ void k_copy(const float4* __restrict__ in, float4* __restrict__ out, size_t n4) {
    size_t i = (size_t)blockIdx.x * blockDim.x + threadIdx.x;
    size_t stride = (size_t)gridDim.x * blockDim.x;
    for (; i < n4; i += stride) out[i] = in[i];
}

__global__ void k_init(int total) {
    int i = blockIdx.x * blockDim.x + threadIdx.x;
    int stride = gridDim.x * blockDim.x;
    for (; i < total; i += stride) g_lastpos[i] = -1;
    if (blockIdx.x == 0 && threadIdx.x < RMAX) {
        g_cnt[threadIdx.x] = 0;
        g_cursor[threadIdx.x] = 0;
    }
}

__global__ void k_encT(const float* __restrict__ encW, const float* __restrict__ encb,
                       int R, int T) {
    int i = blockIdx.x * blockDim.x + threadIdx.x;
    int total = R * T * HH;
    if (i >= total) return;
    int h = i % HH;
    int t = (i / HH) % T;
    int r = i / (HH * T);
    g_encT[i] = encW[(size_t)(r * HH + h) * T + t] + encb[r * HH + h];
}

// Build fragment-major bf16 hi/lo weight tensor + combined biases.
// Gate rows: 0-255 folded r/z (W_ih + W_hh for k>=128), 256-383 n (W_ih),
//            384-511 hn (W_hh n rows, zero for k<128).
__global__ void k_prep(const float* __restrict__ W_ih, const float* __restrict__ W_hh,
                       const float* __restrict__ b_ih, const float* __restrict__ b_hh,
                       int R) {
    int i = blockIdx.x * blockDim.x + threadIdx.x;
    int total = R * 2 * 16 * 16 * 32;
    if (i < total) {
        int lane = i & 31;
        int mt   = (i >> 5) & 15;
        int ks16 = (i >> 9) & 15;
        int nh   = (i >> 13) & 1;
        int r    = i >> 14;
        int g    = lane >> 2;
        int tig  = lane & 3;
        float h1[4][2], h2[4][2];
        #pragma unroll
        for (int ai = 0; ai < 4; ai++) {
            #pragma unroll
            for (int el = 0; el < 2; el++) {
                int m_local = mt * 16 + g + (ai & 1) * 8;
                int k = ks16 * 16 + 2 * tig + (ai >> 1) * 8 + el;
                int row = nh * 256 + m_local;
                float v;
                if (row < 2 * HH) {
                    v = W_ih[((size_t)r * G3 + row) * HH2 + k];
                    if (k >= HH) v += W_hh[((size_t)r * G3 + row) * HH + (k - HH)];
                } else if (row < G3) {
                    v = W_ih[((size_t)r * G3 + row) * HH2 + k];
                } else {
                    int col = row - G3;
                    v = (k >= HH) ? W_hh[((size_t)r * G3 + 2 * HH + col) * HH + (k - HH)] : 0.f;
                }
                float h = bf16rt(v);
                h1[ai][el] = h;
                h2[ai][el] = v - h;
            }
        }
        uint4 hi = make_uint4(pack_bf16x2(h1[0][0], h1[0][1]), pack_bf16x2(h1[1][0], h1[1][1]),
                              pack_bf16x2(h1[2][0], h1[2][1]), pack_bf16x2(h1[3][0], h1[3][1]));
        uint4 lo = make_uint4(pack_bf16x2(h2[0][0], h2[0][1]), pack_bf16x2(h2[1][0], h2[1][1]),
                              pack_bf16x2(h2[2][0], h2[2][1]), pack_bf16x2(h2[3][0], h2[3][1]));
        size_t base = (size_t)(r * 2 + nh) * AFRAG_PER_NH + (size_t)((ks16 * 16 + mt) * 2) * 32 + lane;
        g_Afrag[base]      = hi;
        g_Afrag[base + 32] = lo;
    }
    if (i < R * G3) {
        int col3 = i % G3;
        int r    = i / G3;
        int g    = col3 >> 7;
        g_bc[i] = b_ih[i] + ((g < 2) ? b_hh[i] : 0.f);
        if (g == 2) g_bhn[r * HH + (col3 & 127)] = b_hh[i];
    }
}

__global__ void k_count(const int* __restrict__ rel, const int* __restrict__ src,
                        int E, int N) {
    int i = blockIdx.x * blockDim.x + threadIdx.x;
    if (i < E)
        atomicMax(&g_lastpos[(size_t)rel[i] * N + src[i]], i);
}

// count winning (last) edges per relation
__global__ void k_count2(const int* __restrict__ rel, const int* __restrict__ src,
                         int E, int N) {
    __shared__ int sc[RMAX];
    if (threadIdx.x < RMAX) sc[threadIdx.x] = 0;
    __syncthreads();
    int i = blockIdx.x * blockDim.x + threadIdx.x;
    if (i < E) {
        int r = rel[i];
        if (g_lastpos[(size_t)r * N + src[i]] == i)
            atomicAdd(&sc[r], 1);
    }
    __syncthreads();
    if (threadIdx.x < RMAX && sc[threadIdx.x])
        atomicAdd(&g_cnt[threadIdx.x], sc[threadIdx.x]);
}

__global__ void k_scan(int R) {
    if (threadIdx.x == 0) {
        int acc = 0;
        for (int r = 0; r < R; r++) {
            g_off[r] = acc;
            g_cursor[r] = acc;
            acc += g_cnt[r];
        }
        g_off[R] = acc;
    }
}

// group WINNING edges by relation
__global__ void k_order(const int* __restrict__ rel, const int* __restrict__ src,
                        int E, int N) {
    __shared__ int sc[RMAX], sbase[RMAX];
    if (threadIdx.x < RMAX) sc[threadIdx.x] = 0;
    __syncthreads();
    int i = blockIdx.x * blockDim.x + threadIdx.x;
    int r = 0, pos = 0;
    bool valid = false;
    if (i < E) {
        r = rel[i];
        valid = (g_lastpos[(size_t)r * N + src[i]] == i);
        if (valid) pos = atomicAdd(&sc[r], 1);
    }
    __syncthreads();
    if (threadIdx.x < RMAX && sc[threadIdx.x])
        sbase[threadIdx.x] = atomicAdd(&g_cursor[threadIdx.x], sc[threadIdx.x]);
    __syncthreads();
    if (valid) g_order[sbase[r] + pos] = i;
}

__global__ void k_build_x(const float* __restrict__ prev, const int* __restrict__ src,
                          const int* __restrict__ dst, const int* __restrict__ rel,
                          const int* __restrict__ t_edge, const int* __restrict__ ctp,
                          int E, int N, int T) {
    int i = blockIdx.x * blockDim.x + threadIdx.x;
    if (i >= E * HH) return;
    int e = i >> 7;
    int h = i & (HH - 1);
    int r = rel[e];
    int ct = ctp ? ctp[0] : 100;
    int b = min(ct - t_edge[e], T - 1);
    float enc = g_encT[(r * T + b) * HH + h];
    float uj = prev[((size_t)r * N + dst[e]) * HH + h];
    float ui = prev[((size_t)r * N + src[e]) * HH + h];
    g_x[(size_t)e * HH2 + h]      = enc + uj;
    g_x[(size_t)e * HH2 + HH + h] = ui;
}

// -------- tensor-core GEMM: Y[e, nh*256 .. +256] = X[e,:] . W^T (bf16x3) --------
// smem: sX [128][XS2] floats + sBf [4*16*32] uint4 + sEid[128]
#define SX_F    (MT_E * XS2)
#define SBF_U4  (4 * 16 * 32)
#define SMEM_MMA (SX_F * 4 + SBF_U4 * 16 + MT_E * 4)

__global__ void __launch_bounds__(TPB, 1)
k_gru_mma() {
    int r  = blockIdx.x;
    int nh = blockIdx.z;
    int begin = g_off[r], end = g_off[r + 1];
    int base = begin + blockIdx.y * MT_E;
    if (base >= end) return;
    int mE = min(MT_E, end - base);
    int tid = threadIdx.x;
    int w = tid >> 5, lane = tid & 31;
    int g = lane >> 2, tig = lane & 3;

    extern __shared__ float sm[];
    float* sX   = sm;                          // [m][k-chunk] stride XS2
    uint4* sBf  = (uint4*)(sm + SX_F);         // [ksl][nt][lane]
    int*   sEid = (int*)(sBf + SBF_U4);

    if (tid < MT_E)
        sEid[tid] = (tid < mE) ? g_order[base + tid] : -1;

    const float4* gx4 = (const float4*)g_x;
    const uint4* Ab = g_Afrag + (size_t)(r * 2 + nh) * AFRAG_PER_NH;

    float acc[16][4];
    #pragma unroll
    for (int b = 0; b < 16; b++)
        #pragma unroll
        for (int cc = 0; cc < 4; cc++) acc[b][cc] = 0.f;

    for (int kc = 0; kc < 4; kc++) {
        __syncthreads();   // protect sX/sBf from previous iteration readers
        // ---- load X chunk [128 edges][64 k] (coalesced float4) ----
        #pragma unroll
        for (int it = 0; it < 4; it++) {
            int s = tid + it * TPB;            // 0..2047
            int row = s >> 4, j = s & 15;
            int e = sEid[row];
            float4 v = make_float4(0.f, 0.f, 0.f, 0.f);
            if (e >= 0) v = gx4[(size_t)e * 64 + kc * 16 + j];
            *(float4*)&sX[row * XS2 + 4 * j] = v;
        }
        __syncthreads();
        // ---- build bf16 B fragments once: (b0h1,b1h1,b0h2,b1h2) ----
        #pragma unroll
        for (int it = 0; it < 4; it++) {
            int s = tid + it * TPB;            // 0..2047
            int l2  = s & 31;
            int nt2 = (s >> 5) & 15;
            int ks2 = s >> 9;                  // 0..3
            int g2 = l2 >> 2, t2 = l2 & 3;
            const float* xr = &sX[(nt2 * 8 + g2) * XS2 + ks2 * 16 + 2 * t2];
            float v00 = xr[0], v01 = xr[1], v10 = xr[8], v11 = xr[9];
            float h00 = bf16rt(v00), h01 = bf16rt(v01);
            float h10 = bf16rt(v10), h11 = bf16rt(v11);
            sBf[s] = make_uint4(pack_bf16x2(h00, h01), pack_bf16x2(h10, h11),
                                pack_bf16x2(v00 - h00, v01 - h01),
                                pack_bf16x2(v10 - h10, v11 - h11));
        }
        __syncthreads();
        // ---- compute: warp w owns mtile w ----
        #pragma unroll
        for (int ksl = 0; ksl < 4; ksl++) {
            int ks16 = kc * 4 + ksl;
            const uint4* Ap = Ab + (size_t)((ks16 * 16 + w) * 2) * 32 + lane;
            uint4 h4 = Ap[0];
            uint4 l4 = Ap[32];
            uint32_t ahi[4] = {h4.x, h4.y, h4.z, h4.w};
            uint32_t alo[4] = {l4.x, l4.y, l4.z, l4.w};
            #pragma unroll
            for (int nt = 0; nt < 16; nt++) {
                uint4 bf = sBf[(ksl * 16 + nt) * 32 + lane];
                mma16(acc[nt], ahi, bf.x, bf.y);   // h1.w1
                mma16(acc[nt], ahi, bf.z, bf.w);   // h1.w2
                mma16(acc[nt], alo, bf.x, bf.y);   // h2.w1
            }
        }
    }

    // ---- store raw gates to g_y[e][512] ----
    int col = nh * 256 + w * 16 + g;
    #pragma unroll
    for (int nt = 0; nt < 16; nt++) {
        int e0 = sEid[nt * 8 + 2 * tig];
        int e1 = sEid[nt * 8 + 2 * tig + 1];
        if (e0 >= 0) {
            g_y[(size_t)e0 * NB + col]     = acc[nt][0];
            g_y[(size_t)e0 * NB + col + 8] = acc[nt][2];
        }
        if (e1 >= 0) {
            g_y[(size_t)e1 * NB + col]     = acc[nt][1];
            g_y[(size_t)e1 * NB + col + 8] = acc[nt][3];
        }
    }
}

// -------- epilogue: GRU nonlinearity + scatter (compacted winner list) --------
__global__ void __launch_bounds__(HH)
k_epi(const int* __restrict__ rel, const int* __restrict__ src,
      float* __restrict__ out, int N, int R) {
    int idx = blockIdx.x;
    if (idx >= g_off[R]) return;
    int e = g_order[idx];
    int r = rel[e], s = src[e];
    int col = threadIdx.x;
    float yr = g_y[(size_t)e * NB + col];
    float yz = g_y[(size_t)e * NB + HH + col];
    float yn = g_y[(size_t)e * NB + 2 * HH + col];
    float yh = g_y[(size_t)e * NB + G3 + col];
    float rg = 1.f / (1.f + expf(-(yr + g_bc[r * G3 + col])));
    float zg = 1.f / (1.f + expf(-(yz + g_bc[r * G3 + HH + col])));
    float ng = tanhf(yn + g_bc[r * G3 + 2 * HH + col] + rg * (yh + g_bhn[r * HH + col]));
    float hp = g_x[(size_t)e * HH2 + HH + col];
    out[((size_t)r * N + s) * HH + col] = (1.f - zg) * ng + zg * hp;
}

// -------- launch --------
extern "C" void kernel_launch(void* const* d_in, const int* in_sizes, int n_in,
                              void* d_out, int out_size) {
    const float* prev  = (const float*)d_in[0];
    const float* encW  = (const float*)d_in[1];
    const float* encb  = (const float*)d_in[2];
    const float* W_ih  = (const float*)d_in[3];
    const float* W_hh  = (const float*)d_in[4];
    const float* b_ih  = (const float*)d_in[5];
    const float* b_hh  = (const float*)d_in[6];
    const int*   src   = (const int*)d_in[7];
    const int*   dst   = (const int*)d_in[8];
    const int*   rel   = (const int*)d_in[9];
    const int*   t_edg = (const int*)d_in[10];
    const int*   ctp   = (n_in > 11) ? (const int*)d_in[11] : nullptr;
    float* out = (float*)d_out;

    int E  = in_sizes[7];
    int b_ih_n = in_sizes[5];                 // R*3H
    int W_hh_n = in_sizes[4];                 // R*3H*H
    int Hd = W_hh_n / b_ih_n;                 // 128
    int Rd = b_ih_n / (3 * Hd);               // 8
    long long prevN = in_sizes[0];
    int Nd = (int)(prevN / ((long long)Rd * Hd));
    int Td = in_sizes[1] / (2 * Rd * Hd);

    // 1) copy prev -> out
    size_t n4 = (size_t)out_size / 4;
    k_copy<<<4736, 256>>>((const float4*)prev, (float4*)out, n4);

    // 2) reset scratch
    int totalLP = Rd * Nd;
    k_init<<<(totalLP + 255) / 256, 256>>>(totalLP);

    // 3) transposed encoder table
    int encN = Rd * Td * Hd;
    k_encT<<<(encN + 255) / 256, 256>>>(encW, encb, Rd, Td);

    // 4) fragment-major bf16 hi/lo weights + biases
    int prepN = Rd * 2 * 16 * 16 * 32;
    k_prep<<<(prepN + 255) / 256, 256>>>(W_ih, W_hh, b_ih, b_hh, Rd);

    // 5) lastpos
    k_count<<<(E + 255) / 256, 256>>>(rel, src, E, Nd);

    // 6) count winners per relation
    k_count2<<<(E + 255) / 256, 256>>>(rel, src, E, Nd);

    // 7) scan
    k_scan<<<1, 32>>>(Rd);

    // 8) group winning edges by relation
    k_order<<<(E + 255) / 256, 256>>>(rel, src, E, Nd);

    // 9) build x = [enc + u_j, u_i]
    int bxN = E * Hd;
    k_build_x<<<(bxN + 255) / 256, 256>>>(prev, src, dst, rel, t_edg, ctp, E, Nd, Td);

    // 10) tensor-core GEMM (mma.sync bf16x3) -> raw gates in g_y
    cudaFuncSetAttribute(k_gru_mma, cudaFuncAttributeMaxDynamicSharedMemorySize, SMEM_MMA);
    dim3 grid(Rd, (E + MT_E - 1) / MT_E, 2);
    k_gru_mma<<<grid, TPB, SMEM_MMA>>>();

    // 11) epilogue: nonlinearity + scatter
    k_epi<<<E, HH>>>(rel, src, out, Nd, Rd);
}